// round 6
// baseline (speedup 1.0000x reference)
#include <cuda_runtime.h>
#include <cuda_bf16.h>
#include <math.h>
#include <stdint.h>

#define SEQ   3840
#define DIM   1536
#define NH    12
#define HD    128
#define HG    20
#define WG    24
#define D_F   22
#define D_FH  43

typedef unsigned long long u64;

// ---------------- scratch (device globals; no runtime allocation) -------------
__device__ float g_q[SEQ * DIM];
__device__ float g_k[SEQ * DIM];
__device__ float g_v[SEQ * DIM];
__device__ float g_att[SEQ * DIM];

__device__ __nv_bfloat16 g_xh[SEQ * DIM], g_xl[SEQ * DIM];       // x split
__device__ __nv_bfloat16 g_ah[SEQ * DIM], g_al[SEQ * DIM];       // att split
__device__ __nv_bfloat16 g_wh[4][DIM * DIM], g_wl[4][DIM * DIM]; // W^T splits

// ---------------- f32x2 helpers (for SIMT attention) --------------------------
__device__ __forceinline__ u64 fma2(u64 a, u64 b, u64 c) {
    u64 d;
    asm("fma.rn.f32x2 %0, %1, %2, %3;" : "=l"(d) : "l"(a), "l"(b), "l"(c));
    return d;
}
__device__ __forceinline__ u64 mul2(u64 a, u64 b) {
    u64 d;
    asm("mul.rn.f32x2 %0, %1, %2;" : "=l"(d) : "l"(a), "l"(b));
    return d;
}
__device__ __forceinline__ u64 dup2(float a) {
    u64 d;
    asm("mov.b64 %0, {%1, %1};" : "=l"(d) : "f"(a));
    return d;
}
__device__ __forceinline__ float2 unpk(u64 a) {
    float2 f;
    asm("mov.b64 {%0, %1}, %2;" : "=f"(f.x), "=f"(f.y) : "l"(a));
    return f;
}

// ---------------- cp.async helpers --------------------------------------------
__device__ __forceinline__ uint32_t smem_u32(const void* p) {
    uint32_t a;
    asm("{ .reg .u64 t; cvta.to.shared.u64 t, %1; cvt.u32.u64 %0, t; }"
        : "=r"(a) : "l"(p));
    return a;
}
__device__ __forceinline__ void cpasync16(uint32_t saddr, const void* g) {
    asm volatile("cp.async.cg.shared.global [%0], [%1], 16;"
                 :: "r"(saddr), "l"(g) : "memory");
}
#define CP_COMMIT() asm volatile("cp.async.commit_group;" ::: "memory")
#define CP_WAIT0()  asm volatile("cp.async.wait_group 0;" ::: "memory")

// ---------------- mma.sync m16n8k16 bf16 --------------------------------------
__device__ __forceinline__ void mma16816(float& d0, float& d1, float& d2, float& d3,
                                         uint32_t a0, uint32_t a1, uint32_t a2,
                                         uint32_t a3, uint32_t b0, uint32_t b1) {
    asm volatile(
        "mma.sync.aligned.m16n8k16.row.col.f32.bf16.bf16.f32 "
        "{%0,%1,%2,%3}, {%4,%5,%6,%7}, {%8,%9}, {%0,%1,%2,%3};"
        : "+f"(d0), "+f"(d1), "+f"(d2), "+f"(d3)
        : "r"(a0), "r"(a1), "r"(a2), "r"(a3), "r"(b0), "r"(b1));
}

// ---------------- prep: split activations into bf16 hi/lo ---------------------
__global__ void split_act(const float* __restrict__ xsrc, int which)
{
    const float* src = (which == 0) ? xsrc : g_att;
    __nv_bfloat16* dh = (which == 0) ? g_xh : g_ah;
    __nv_bfloat16* dl = (which == 0) ? g_xl : g_al;
    int i = (blockIdx.x * 256 + threadIdx.x) * 4;
    float4 v = *(const float4*)&src[i];
    __nv_bfloat16 h0 = __float2bfloat16(v.x), h1 = __float2bfloat16(v.y);
    __nv_bfloat16 h2 = __float2bfloat16(v.z), h3 = __float2bfloat16(v.w);
    __nv_bfloat16 l0 = __float2bfloat16(v.x - __bfloat162float(h0));
    __nv_bfloat16 l1 = __float2bfloat16(v.y - __bfloat162float(h1));
    __nv_bfloat16 l2 = __float2bfloat16(v.z - __bfloat162float(h2));
    __nv_bfloat16 l3 = __float2bfloat16(v.w - __bfloat162float(h3));
    ushort4 hh, ll;
    hh.x = *(unsigned short*)&h0; hh.y = *(unsigned short*)&h1;
    hh.z = *(unsigned short*)&h2; hh.w = *(unsigned short*)&h3;
    ll.x = *(unsigned short*)&l0; ll.y = *(unsigned short*)&l1;
    ll.z = *(unsigned short*)&l2; ll.w = *(unsigned short*)&l3;
    *(ushort4*)&dh[i] = hh;
    *(ushort4*)&dl[i] = ll;
}

// ---------------- prep: transpose + split weights ------------------------------
// in: W[K][N] f32;  out: g_wh/g_wl[z][N][K] bf16
__global__ void transpose_split(const float* __restrict__ w0,
                                const float* __restrict__ w1,
                                const float* __restrict__ w2,
                                const float* __restrict__ w3)
{
    const float* W = (blockIdx.z == 0) ? w0 : (blockIdx.z == 1) ? w1
                   : (blockIdx.z == 2) ? w2 : w3;
    __nv_bfloat16* Oh = g_wh[blockIdx.z];
    __nv_bfloat16* Ol = g_wl[blockIdx.z];

    __shared__ float t[32][33];
    int k0 = blockIdx.y * 32, n0 = blockIdx.x * 32;
    int tx = threadIdx.x, ty = threadIdx.y;
#pragma unroll
    for (int j = 0; j < 4; j++)
        t[ty + j * 8][tx] = W[(size_t)(k0 + ty + j * 8) * DIM + n0 + tx];
    __syncthreads();
#pragma unroll
    for (int j = 0; j < 4; j++) {
        float v = t[tx][ty + j * 8];
        __nv_bfloat16 h = __float2bfloat16(v);
        __nv_bfloat16 l = __float2bfloat16(v - __bfloat162float(h));
        size_t o = (size_t)(n0 + ty + j * 8) * DIM + k0 + tx;
        Oh[o] = h;
        Ol[o] = l;
    }
}

// ---------------- mma.sync bf16x3 GEMM -----------------------------------------
// C[3840,1536] = A @ W^T(stored [N][K]) + bias. 128x128 CTA tile, BK=32.
// 8 warps in 2x4; each warp 64x32 (4 mtiles x 4 ntiles of m16n8k16).
#define TS 40   // smem row stride (bf16) -> conflict-free LDS.32 fragments

__global__ __launch_bounds__(256, 2)
void hgemm(int asel, int wsel, const float* __restrict__ bias,
           float* __restrict__ Cout, int csel)
{
    const __nv_bfloat16* Agh = asel ? g_ah : g_xh;
    const __nv_bfloat16* Agl = asel ? g_al : g_xl;
    const __nv_bfloat16* Bgh = g_wh[wsel];
    const __nv_bfloat16* Bgl = g_wl[wsel];
    float* C = (csel == 0) ? g_q : (csel == 1) ? g_k : (csel == 2) ? g_v : Cout;

    __shared__ __nv_bfloat16 sAh[128 * TS], sAl[128 * TS];
    __shared__ __nv_bfloat16 sBh[128 * TS], sBl[128 * TS];

    int tid = threadIdx.x, wid = tid >> 5, lid = tid & 31;
    int wm = wid >> 2, wn = wid & 3;               // warp tile: 64m x 32n
    int g = lid >> 2, tg = lid & 3;
    int m0 = blockIdx.y * 128, n0 = blockIdx.x * 128;

    uint32_t uAh = smem_u32(sAh), uAl = smem_u32(sAl);
    uint32_t uBh = smem_u32(sBh), uBl = smem_u32(sBl);

    // copy map: 512 16B segments per tile; 2 per thread
    int r0 = tid >> 2, s0 = tid & 3;
    int r1 = (tid + 256) >> 2, s1 = tid & 3;
    uint32_t so0 = r0 * (TS * 2) + s0 * 16;
    uint32_t so1 = r1 * (TS * 2) + s1 * 16;

    float acc[4][4][4];
#pragma unroll
    for (int t = 0; t < 4; t++)
#pragma unroll
        for (int u = 0; u < 4; u++)
#pragma unroll
            for (int c = 0; c < 4; c++) acc[t][u][c] = 0.f;

    const __nv_bfloat16* Asm = sAh;  (void)Asm;

    for (int ch = 0; ch < DIM / 32; ch++) {
        size_t ga0 = (size_t)(m0 + r0) * DIM + ch * 32 + s0 * 8;
        size_t ga1 = (size_t)(m0 + r1) * DIM + ch * 32 + s1 * 8;
        size_t gb0 = (size_t)(n0 + r0) * DIM + ch * 32 + s0 * 8;
        size_t gb1 = (size_t)(n0 + r1) * DIM + ch * 32 + s1 * 8;
        cpasync16(uAh + so0, &Agh[ga0]);
        cpasync16(uAh + so1, &Agh[ga1]);
        cpasync16(uAl + so0, &Agl[ga0]);
        cpasync16(uAl + so1, &Agl[ga1]);
        cpasync16(uBh + so0, &Bgh[gb0]);
        cpasync16(uBh + so1, &Bgh[gb1]);
        cpasync16(uBl + so0, &Bgl[gb0]);
        cpasync16(uBl + so1, &Bgl[gb1]);
        CP_COMMIT();
        CP_WAIT0();
        __syncthreads();

#pragma unroll
        for (int ks = 0; ks < 2; ks++) {
            int kc = ks * 16 + tg * 2;   // even bf16 col -> 4B aligned
            uint32_t ah[4][4], bh[4][2];
#pragma unroll
            for (int t = 0; t < 4; t++) {
                int ra = wm * 64 + t * 16 + g;
                ah[t][0] = *(uint32_t*)&sAh[ra * TS + kc];
                ah[t][1] = *(uint32_t*)&sAh[(ra + 8) * TS + kc];
                ah[t][2] = *(uint32_t*)&sAh[ra * TS + kc + 8];
                ah[t][3] = *(uint32_t*)&sAh[(ra + 8) * TS + kc + 8];
            }
#pragma unroll
            for (int u = 0; u < 4; u++) {
                int rb = wn * 32 + u * 8 + g;
                bh[u][0] = *(uint32_t*)&sBh[rb * TS + kc];
                bh[u][1] = *(uint32_t*)&sBh[rb * TS + kc + 8];
            }
#pragma unroll
            for (int t = 0; t < 4; t++)
#pragma unroll
                for (int u = 0; u < 4; u++)
                    mma16816(acc[t][u][0], acc[t][u][1], acc[t][u][2], acc[t][u][3],
                             ah[t][0], ah[t][1], ah[t][2], ah[t][3],
                             bh[u][0], bh[u][1]);

            // Ah * Bl
#pragma unroll
            for (int u = 0; u < 4; u++) {
                int rb = wn * 32 + u * 8 + g;
                uint32_t bl0 = *(uint32_t*)&sBl[rb * TS + kc];
                uint32_t bl1 = *(uint32_t*)&sBl[rb * TS + kc + 8];
#pragma unroll
                for (int t = 0; t < 4; t++)
                    mma16816(acc[t][u][0], acc[t][u][1], acc[t][u][2], acc[t][u][3],
                             ah[t][0], ah[t][1], ah[t][2], ah[t][3], bl0, bl1);
            }
            // Al * Bh
#pragma unroll
            for (int t = 0; t < 4; t++) {
                int ra = wm * 64 + t * 16 + g;
                uint32_t al0 = *(uint32_t*)&sAl[ra * TS + kc];
                uint32_t al1 = *(uint32_t*)&sAl[(ra + 8) * TS + kc];
                uint32_t al2 = *(uint32_t*)&sAl[ra * TS + kc + 8];
                uint32_t al3 = *(uint32_t*)&sAl[(ra + 8) * TS + kc + 8];
#pragma unroll
                for (int u = 0; u < 4; u++)
                    mma16816(acc[t][u][0], acc[t][u][1], acc[t][u][2], acc[t][u][3],
                             al0, al1, al2, al3, bh[u][0], bh[u][1]);
            }
        }
        __syncthreads();
    }

    // epilogue: bias + store (float2 per fragment half-row)
#pragma unroll
    for (int t = 0; t < 4; t++) {
        int row = m0 + wm * 64 + t * 16 + g;
#pragma unroll
        for (int u = 0; u < 4; u++) {
            int col = n0 + wn * 32 + u * 8 + tg * 2;
            float2 bv = *(const float2*)&bias[col];
            float2 lo = make_float2(acc[t][u][0] + bv.x, acc[t][u][1] + bv.y);
            float2 hi = make_float2(acc[t][u][2] + bv.x, acc[t][u][3] + bv.y);
            *(float2*)&C[(size_t)row * DIM + col] = lo;
            *(float2*)&C[(size_t)(row + 8) * DIM + col] = hi;
        }
    }
}

// ---------------- RMSNorm + RoPE (in place on g_q / g_k) ----------------------
__global__ void normrope_kernel(const float* __restrict__ nqw,
                                const float* __restrict__ nkw,
                                const float* __restrict__ freqs)
{
    int s = blockIdx.x;
    bool isq = (blockIdx.y == 0);
    float* buf = (isq ? g_q : g_k) + (size_t)s * DIM;
    const float* w = isq ? nqw : nkw;
    float oscale = isq ? 0.08838834764831845f : 1.0f;

    __shared__ float row[DIM];
    __shared__ float red[8];

    int tid = threadIdx.x;
    float ss = 0.f;
    for (int i = tid; i < DIM; i += 256) {
        float v = buf[i];
        row[i] = v;
        ss += v * v;
    }
#pragma unroll
    for (int o = 16; o; o >>= 1) ss += __shfl_xor_sync(0xffffffff, ss, o);
    if ((tid & 31) == 0) red[tid >> 5] = ss;
    __syncthreads();
    if (tid < 8) {
        float t = red[tid];
#pragma unroll
        for (int o = 4; o; o >>= 1) t += __shfl_xor_sync(0xff, t, o);
        if (tid == 0) red[0] = t;
    }
    __syncthreads();
    float r = rsqrtf(red[0] / (float)DIM + 1e-6f);

    int fi = s / (HG * WG);
    int rem = s % (HG * WG);
    int hi = rem / WG;
    int wi = rem % WG;

    for (int p = tid; p < NH * 64; p += 256) {
        int h = p >> 6, c = p & 63;
        int pos = (c < D_F) ? fi : (c < D_FH) ? hi : wi;
        float ang = freqs[pos * 64 + c];
        float sn, cs;
        sincosf(ang, &sn, &cs);
        int j = h * HD + 2 * c;
        float y0 = row[j] * r * w[j];
        float y1 = row[j + 1] * r * w[j + 1];
        buf[j]     = (y0 * cs - y1 * sn) * oscale;
        buf[j + 1] = (y0 * sn + y1 * cs) * oscale;
    }
}

// ---------------- fp32 flash attention, f32x2 ----------------------------------
#define AT_BQ 128
#define AT_BK 64
#define PT_STRIDE 132

__global__ __launch_bounds__(256, 1)
void attn_kernel()
{
    extern __shared__ float sm[];
    float* Qs = sm;                       // 128*128   [d][q]
    float* Ks = Qs + 128 * 128;           // 128*64    [d][k]
    float* Vs = Ks + 128 * 64;            // 64*128    [k][d]
    float* Pt = Vs + 64 * 128;            // 64*132    [k][q]

    int tid = threadIdx.x;
    int h = blockIdx.y;
    int q0 = blockIdx.x * AT_BQ;
    int ty = tid >> 4, tx = tid & 15;

#pragma unroll
    for (int it = 0; it < 16; it++) {
        int idx = tid + it * 256;
        int r = idx & 127, d4 = idx >> 7;
        float4 v = *(const float4*)&g_q[(size_t)(q0 + r) * DIM + h * HD + d4 * 4];
        Qs[(d4 * 4 + 0) * 128 + r] = v.x;
        Qs[(d4 * 4 + 1) * 128 + r] = v.y;
        Qs[(d4 * 4 + 2) * 128 + r] = v.z;
        Qs[(d4 * 4 + 3) * 128 + r] = v.w;
    }

    u64 oacc[8][4];
#pragma unroll
    for (int i = 0; i < 8; i++)
#pragma unroll
        for (int j = 0; j < 4; j++) oacc[i][j] = 0ull;
    float m_run[8], l_run[8];
#pragma unroll
    for (int i = 0; i < 8; i++) { m_run[i] = -1e30f; l_run[i] = 0.f; }

    for (int kb = 0; kb < SEQ / AT_BK; kb++) {
        int k0 = kb * AT_BK;
        __syncthreads();

#pragma unroll
        for (int it = 0; it < 8; it++) {
            int idx = tid + it * 256;
            int r = idx & 63, d4 = idx >> 6;
            float4 v = *(const float4*)&g_k[(size_t)(k0 + r) * DIM + h * HD + d4 * 4];
            Ks[(d4 * 4 + 0) * 64 + r] = v.x;
            Ks[(d4 * 4 + 1) * 64 + r] = v.y;
            Ks[(d4 * 4 + 2) * 64 + r] = v.z;
            Ks[(d4 * 4 + 3) * 64 + r] = v.w;
        }
#pragma unroll
        for (int it = 0; it < 8; it++) {
            int idx = tid + it * 256;
            int r = idx >> 5, d4 = idx & 31;
            *(float4*)&Vs[r * 128 + d4 * 4] =
                *(const float4*)&g_v[(size_t)(k0 + r) * DIM + h * HD + d4 * 4];
        }
        __syncthreads();

        u64 sacc[8][2];
#pragma unroll
        for (int i = 0; i < 8; i++) { sacc[i][0] = 0ull; sacc[i][1] = 0ull; }
#pragma unroll 4
        for (int d = 0; d < 128; d++) {
            float4 a0 = *(float4*)&Qs[d * 128 + ty * 8];
            float4 a1 = *(float4*)&Qs[d * 128 + ty * 8 + 4];
            ulonglong2 bp = *(ulonglong2*)&Ks[d * 64 + tx * 4];
            float av[8] = {a0.x, a0.y, a0.z, a0.w, a1.x, a1.y, a1.z, a1.w};
#pragma unroll
            for (int i = 0; i < 8; i++) {
                u64 ad = dup2(av[i]);
                sacc[i][0] = fma2(ad, bp.x, sacc[i][0]);
                sacc[i][1] = fma2(ad, bp.y, sacc[i][1]);
            }
        }

        float p[8][4];
        float corr[8];
#pragma unroll
        for (int i = 0; i < 8; i++) {
            float2 s0 = unpk(sacc[i][0]);
            float2 s1 = unpk(sacc[i][1]);
            p[i][0] = s0.x; p[i][1] = s0.y; p[i][2] = s1.x; p[i][3] = s1.y;
            float mx = fmaxf(fmaxf(p[i][0], p[i][1]), fmaxf(p[i][2], p[i][3]));
#pragma unroll
            for (int o = 8; o; o >>= 1)
                mx = fmaxf(mx, __shfl_xor_sync(0xffffffffu, mx, o));
            float mnew = fmaxf(m_run[i], mx);
            corr[i] = __expf(m_run[i] - mnew);
            float ls = 0.f;
#pragma unroll
            for (int j = 0; j < 4; j++) {
                p[i][j] = __expf(p[i][j] - mnew);
                ls += p[i][j];
            }
#pragma unroll
            for (int o = 8; o; o >>= 1)
                ls += __shfl_xor_sync(0xffffffffu, ls, o);
            l_run[i] = l_run[i] * corr[i] + ls;
            m_run[i] = mnew;
        }
#pragma unroll
        for (int c = 0; c < 4; c++) {
            int j = tx * 4 + c;
            float4 lo = make_float4(p[0][c], p[1][c], p[2][c], p[3][c]);
            float4 hi = make_float4(p[4][c], p[5][c], p[6][c], p[7][c]);
            *(float4*)&Pt[j * PT_STRIDE + ty * 8] = lo;
            *(float4*)&Pt[j * PT_STRIDE + ty * 8 + 4] = hi;
        }
        __syncthreads();

#pragma unroll
        for (int i = 0; i < 8; i++) {
            u64 cd = dup2(corr[i]);
#pragma unroll
            for (int jp = 0; jp < 4; jp++) oacc[i][jp] = mul2(oacc[i][jp], cd);
        }
#pragma unroll 2
        for (int j = 0; j < AT_BK; j++) {
            float4 p0 = *(float4*)&Pt[j * PT_STRIDE + ty * 8];
            float4 p1 = *(float4*)&Pt[j * PT_STRIDE + ty * 8 + 4];
            ulonglong2 v0 = *(ulonglong2*)&Vs[j * 128 + tx * 8];
            ulonglong2 v1 = *(ulonglong2*)&Vs[j * 128 + tx * 8 + 4];
            float pv[8] = {p0.x, p0.y, p0.z, p0.w, p1.x, p1.y, p1.z, p1.w};
#pragma unroll
            for (int i = 0; i < 8; i++) {
                u64 ad = dup2(pv[i]);
                oacc[i][0] = fma2(ad, v0.x, oacc[i][0]);
                oacc[i][1] = fma2(ad, v0.y, oacc[i][1]);
                oacc[i][2] = fma2(ad, v1.x, oacc[i][2]);
                oacc[i][3] = fma2(ad, v1.y, oacc[i][3]);
            }
        }
    }

#pragma unroll
    for (int i = 0; i < 8; i++) {
        float inv = 1.0f / l_run[i];
        float2 c0 = unpk(oacc[i][0]);
        float2 c1 = unpk(oacc[i][1]);
        float2 c2 = unpk(oacc[i][2]);
        float2 c3 = unpk(oacc[i][3]);
        float4 lo = make_float4(c0.x * inv, c0.y * inv, c1.x * inv, c1.y * inv);
        float4 hi = make_float4(c2.x * inv, c2.y * inv, c3.x * inv, c3.y * inv);
        float* dst = &g_att[(size_t)(q0 + ty * 8 + i) * DIM + h * HD + tx * 8];
        *(float4*)&dst[0] = lo;
        *(float4*)&dst[4] = hi;
    }
}

// ---------------- launch ------------------------------------------------------
extern "C" void kernel_launch(void* const* d_in, const int* in_sizes, int n_in,
                              void* d_out, int out_size)
{
    const float* x    = (const float*)d_in[0];
    const float* q_w  = (const float*)d_in[1];
    const float* q_b  = (const float*)d_in[2];
    const float* k_w  = (const float*)d_in[3];
    const float* k_b  = (const float*)d_in[4];
    const float* v_w  = (const float*)d_in[5];
    const float* v_b  = (const float*)d_in[6];
    const float* o_w  = (const float*)d_in[7];
    const float* o_b  = (const float*)d_in[8];
    const float* nqw  = (const float*)d_in[9];
    const float* nkw  = (const float*)d_in[10];
    const float* freqs = (const float*)d_in[11];
    float* out = (float*)d_out;

    size_t asm_sz = (size_t)(128 * 128 + 128 * 64 + 64 * 128 + 64 * PT_STRIDE)
                    * sizeof(float);
    cudaFuncSetAttribute(attn_kernel, cudaFuncAttributeMaxDynamicSharedMemorySize,
                         (int)asm_sz);

    split_act<<<SEQ * DIM / 1024, 256>>>(x, 0);
    transpose_split<<<dim3(DIM / 32, DIM / 32, 4), dim3(32, 8)>>>(q_w, k_w, v_w, o_w);

    dim3 gg(DIM / 128, SEQ / 128);
    hgemm<<<gg, 256>>>(0, 0, q_b, nullptr, 0);
    hgemm<<<gg, 256>>>(0, 1, k_b, nullptr, 1);
    hgemm<<<gg, 256>>>(0, 2, v_b, nullptr, 2);

    normrope_kernel<<<dim3(SEQ, 2), 256>>>(nqw, nkw, freqs);

    attn_kernel<<<dim3(SEQ / AT_BQ, NH), 256, asm_sz>>>();

    split_act<<<SEQ * DIM / 1024, 256>>>(nullptr, 1);
    hgemm<<<gg, 256>>>(1, 3, o_b, out, 3);
}

// round 7
// speedup vs baseline: 1.9069x; 1.9069x over previous
#include <cuda_runtime.h>
#include <cuda_bf16.h>
#include <math.h>
#include <stdint.h>

#define SEQ   3840
#define DIM   1536
#define NH    12
#define HD    128
#define HG    20
#define WG    24
#define D_F   22
#define D_FH  43

typedef unsigned long long u64;

// ---------------- scratch (device globals; no runtime allocation) -------------
__device__ float g_q[SEQ * DIM];
__device__ float g_k[SEQ * DIM];
__device__ float g_v[SEQ * DIM];
__device__ float g_att[SEQ * DIM];

__device__ __nv_bfloat16 g_xh[SEQ * DIM], g_xl[SEQ * DIM];       // x split
__device__ __nv_bfloat16 g_ah[SEQ * DIM], g_al[SEQ * DIM];       // att split
__device__ __nv_bfloat16 g_wh[4][DIM * DIM], g_wl[4][DIM * DIM]; // W^T splits

// attention operands, head-major bf16 hi/lo
__device__ __nv_bfloat16 g_qbh[NH * SEQ * HD], g_qbl[NH * SEQ * HD]; // [h][s][d]
__device__ __nv_bfloat16 g_kbh[NH * SEQ * HD], g_kbl[NH * SEQ * HD]; // [h][s][d]
__device__ __nv_bfloat16 g_vth[NH * HD * SEQ], g_vtl[NH * HD * SEQ]; // [h][d][s]

// ---------------- helpers -----------------------------------------------------
__device__ __forceinline__ uint32_t smem_u32(const void* p) {
    uint32_t a;
    asm("{ .reg .u64 t; cvta.to.shared.u64 t, %1; cvt.u32.u64 %0, t; }"
        : "=r"(a) : "l"(p));
    return a;
}
__device__ __forceinline__ void cpasync16(uint32_t saddr, const void* g) {
    asm volatile("cp.async.cg.shared.global [%0], [%1], 16;"
                 :: "r"(saddr), "l"(g) : "memory");
}
#define CP_COMMIT() asm volatile("cp.async.commit_group;" ::: "memory")
#define CP_WAIT0()  asm volatile("cp.async.wait_group 0;" ::: "memory")
#define CP_WAIT1()  asm volatile("cp.async.wait_group 1;" ::: "memory")

__device__ __forceinline__ void mma16816(float& d0, float& d1, float& d2, float& d3,
                                         uint32_t a0, uint32_t a1, uint32_t a2,
                                         uint32_t a3, uint32_t b0, uint32_t b1) {
    asm volatile(
        "mma.sync.aligned.m16n8k16.row.col.f32.bf16.bf16.f32 "
        "{%0,%1,%2,%3}, {%4,%5,%6,%7}, {%8,%9}, {%0,%1,%2,%3};"
        : "+f"(d0), "+f"(d1), "+f"(d2), "+f"(d3)
        : "r"(a0), "r"(a1), "r"(a2), "r"(a3), "r"(b0), "r"(b1));
}

// ---------------- prep: split activations into bf16 hi/lo ---------------------
__global__ void split_act(const float* __restrict__ xsrc, int which)
{
    const float* src = (which == 0) ? xsrc : g_att;
    __nv_bfloat16* dh = (which == 0) ? g_xh : g_ah;
    __nv_bfloat16* dl = (which == 0) ? g_xl : g_al;
    int i = (blockIdx.x * 256 + threadIdx.x) * 4;
    float4 v = *(const float4*)&src[i];
    __nv_bfloat16 h0 = __float2bfloat16(v.x), h1 = __float2bfloat16(v.y);
    __nv_bfloat16 h2 = __float2bfloat16(v.z), h3 = __float2bfloat16(v.w);
    __nv_bfloat16 l0 = __float2bfloat16(v.x - __bfloat162float(h0));
    __nv_bfloat16 l1 = __float2bfloat16(v.y - __bfloat162float(h1));
    __nv_bfloat16 l2 = __float2bfloat16(v.z - __bfloat162float(h2));
    __nv_bfloat16 l3 = __float2bfloat16(v.w - __bfloat162float(h3));
    ushort4 hh, ll;
    hh.x = *(unsigned short*)&h0; hh.y = *(unsigned short*)&h1;
    hh.z = *(unsigned short*)&h2; hh.w = *(unsigned short*)&h3;
    ll.x = *(unsigned short*)&l0; ll.y = *(unsigned short*)&l1;
    ll.z = *(unsigned short*)&l2; ll.w = *(unsigned short*)&l3;
    *(ushort4*)&dh[i] = hh;
    *(ushort4*)&dl[i] = ll;
}

// ---------------- prep: transpose + split weights ------------------------------
__global__ void transpose_split(const float* __restrict__ w0,
                                const float* __restrict__ w1,
                                const float* __restrict__ w2,
                                const float* __restrict__ w3)
{
    const float* W = (blockIdx.z == 0) ? w0 : (blockIdx.z == 1) ? w1
                   : (blockIdx.z == 2) ? w2 : w3;
    __nv_bfloat16* Oh = g_wh[blockIdx.z];
    __nv_bfloat16* Ol = g_wl[blockIdx.z];

    __shared__ float t[32][33];
    int k0 = blockIdx.y * 32, n0 = blockIdx.x * 32;
    int tx = threadIdx.x, ty = threadIdx.y;
#pragma unroll
    for (int j = 0; j < 4; j++)
        t[ty + j * 8][tx] = W[(size_t)(k0 + ty + j * 8) * DIM + n0 + tx];
    __syncthreads();
#pragma unroll
    for (int j = 0; j < 4; j++) {
        float v = t[tx][ty + j * 8];
        __nv_bfloat16 h = __float2bfloat16(v);
        __nv_bfloat16 l = __float2bfloat16(v - __bfloat162float(h));
        size_t o = (size_t)(n0 + ty + j * 8) * DIM + k0 + tx;
        Oh[o] = h;
        Ol[o] = l;
    }
}

// ---------------- prep: transpose V to [h][d][s] bf16 hi/lo --------------------
__global__ void transpose_v()
{
    __shared__ float t[32][33];
    int s0 = blockIdx.x * 32, d0 = blockIdx.y * 32, h = blockIdx.z;
    int tx = threadIdx.x, ty = threadIdx.y;
#pragma unroll
    for (int j = 0; j < 4; j++)
        t[ty + j * 8][tx] = g_v[(size_t)(s0 + ty + j * 8) * DIM + h * HD + d0 + tx];
    __syncthreads();
#pragma unroll
    for (int j = 0; j < 4; j++) {
        float v = t[tx][ty + j * 8];
        __nv_bfloat16 hb = __float2bfloat16(v);
        __nv_bfloat16 lb = __float2bfloat16(v - __bfloat162float(hb));
        size_t o = ((size_t)h * HD + d0 + ty + j * 8) * SEQ + s0 + tx;
        g_vth[o] = hb;
        g_vtl[o] = lb;
    }
}

// ---------------- mma.sync bf16x3 GEMM (unchanged, proven) ---------------------
#define TS 40

__global__ __launch_bounds__(256, 2)
void hgemm(int asel, int wsel, const float* __restrict__ bias,
           float* __restrict__ Cout, int csel)
{
    const __nv_bfloat16* Agh = asel ? g_ah : g_xh;
    const __nv_bfloat16* Agl = asel ? g_al : g_xl;
    const __nv_bfloat16* Bgh = g_wh[wsel];
    const __nv_bfloat16* Bgl = g_wl[wsel];
    float* C = (csel == 0) ? g_q : (csel == 1) ? g_k : (csel == 2) ? g_v : Cout;

    __shared__ __nv_bfloat16 sAh[128 * TS], sAl[128 * TS];
    __shared__ __nv_bfloat16 sBh[128 * TS], sBl[128 * TS];

    int tid = threadIdx.x, wid = tid >> 5, lid = tid & 31;
    int wm = wid >> 2, wn = wid & 3;
    int g = lid >> 2, tg = lid & 3;
    int m0 = blockIdx.y * 128, n0 = blockIdx.x * 128;

    uint32_t uAh = smem_u32(sAh), uAl = smem_u32(sAl);
    uint32_t uBh = smem_u32(sBh), uBl = smem_u32(sBl);

    int r0 = tid >> 2, s0 = tid & 3;
    int r1 = (tid + 256) >> 2, s1 = tid & 3;
    uint32_t so0 = r0 * (TS * 2) + s0 * 16;
    uint32_t so1 = r1 * (TS * 2) + s1 * 16;

    float acc[4][4][4];
#pragma unroll
    for (int t = 0; t < 4; t++)
#pragma unroll
        for (int u = 0; u < 4; u++)
#pragma unroll
            for (int c = 0; c < 4; c++) acc[t][u][c] = 0.f;

    for (int ch = 0; ch < DIM / 32; ch++) {
        size_t ga0 = (size_t)(m0 + r0) * DIM + ch * 32 + s0 * 8;
        size_t ga1 = (size_t)(m0 + r1) * DIM + ch * 32 + s1 * 8;
        size_t gb0 = (size_t)(n0 + r0) * DIM + ch * 32 + s0 * 8;
        size_t gb1 = (size_t)(n0 + r1) * DIM + ch * 32 + s1 * 8;
        cpasync16(uAh + so0, &Agh[ga0]);
        cpasync16(uAh + so1, &Agh[ga1]);
        cpasync16(uAl + so0, &Agl[ga0]);
        cpasync16(uAl + so1, &Agl[ga1]);
        cpasync16(uBh + so0, &Bgh[gb0]);
        cpasync16(uBh + so1, &Bgh[gb1]);
        cpasync16(uBl + so0, &Bgl[gb0]);
        cpasync16(uBl + so1, &Bgl[gb1]);
        CP_COMMIT();
        CP_WAIT0();
        __syncthreads();

#pragma unroll
        for (int ks = 0; ks < 2; ks++) {
            int kc = ks * 16 + tg * 2;
            uint32_t ah[4][4], bh[4][2];
#pragma unroll
            for (int t = 0; t < 4; t++) {
                int ra = wm * 64 + t * 16 + g;
                ah[t][0] = *(uint32_t*)&sAh[ra * TS + kc];
                ah[t][1] = *(uint32_t*)&sAh[(ra + 8) * TS + kc];
                ah[t][2] = *(uint32_t*)&sAh[ra * TS + kc + 8];
                ah[t][3] = *(uint32_t*)&sAh[(ra + 8) * TS + kc + 8];
            }
#pragma unroll
            for (int u = 0; u < 4; u++) {
                int rb = wn * 32 + u * 8 + g;
                bh[u][0] = *(uint32_t*)&sBh[rb * TS + kc];
                bh[u][1] = *(uint32_t*)&sBh[rb * TS + kc + 8];
            }
#pragma unroll
            for (int t = 0; t < 4; t++)
#pragma unroll
                for (int u = 0; u < 4; u++)
                    mma16816(acc[t][u][0], acc[t][u][1], acc[t][u][2], acc[t][u][3],
                             ah[t][0], ah[t][1], ah[t][2], ah[t][3],
                             bh[u][0], bh[u][1]);
#pragma unroll
            for (int u = 0; u < 4; u++) {
                int rb = wn * 32 + u * 8 + g;
                uint32_t bl0 = *(uint32_t*)&sBl[rb * TS + kc];
                uint32_t bl1 = *(uint32_t*)&sBl[rb * TS + kc + 8];
#pragma unroll
                for (int t = 0; t < 4; t++)
                    mma16816(acc[t][u][0], acc[t][u][1], acc[t][u][2], acc[t][u][3],
                             ah[t][0], ah[t][1], ah[t][2], ah[t][3], bl0, bl1);
            }
#pragma unroll
            for (int t = 0; t < 4; t++) {
                int ra = wm * 64 + t * 16 + g;
                uint32_t al0 = *(uint32_t*)&sAl[ra * TS + kc];
                uint32_t al1 = *(uint32_t*)&sAl[(ra + 8) * TS + kc];
                uint32_t al2 = *(uint32_t*)&sAl[ra * TS + kc + 8];
                uint32_t al3 = *(uint32_t*)&sAl[(ra + 8) * TS + kc + 8];
#pragma unroll
                for (int u = 0; u < 4; u++)
                    mma16816(acc[t][u][0], acc[t][u][1], acc[t][u][2], acc[t][u][3],
                             al0, al1, al2, al3, bh[u][0], bh[u][1]);
            }
        }
        __syncthreads();
    }

#pragma unroll
    for (int t = 0; t < 4; t++) {
        int row = m0 + wm * 64 + t * 16 + g;
#pragma unroll
        for (int u = 0; u < 4; u++) {
            int col = n0 + wn * 32 + u * 8 + tg * 2;
            float2 bv = *(const float2*)&bias[col];
            float2 lo = make_float2(acc[t][u][0] + bv.x, acc[t][u][1] + bv.y);
            float2 hi = make_float2(acc[t][u][2] + bv.x, acc[t][u][3] + bv.y);
            *(float2*)&C[(size_t)row * DIM + col] = lo;
            *(float2*)&C[(size_t)(row + 8) * DIM + col] = hi;
        }
    }
}

// ---------------- RMSNorm + RoPE -> bf16 hi/lo head-major ----------------------
__global__ void normrope_kernel(const float* __restrict__ nqw,
                                const float* __restrict__ nkw,
                                const float* __restrict__ freqs)
{
    int s = blockIdx.x;
    bool isq = (blockIdx.y == 0);
    const float* buf = (isq ? g_q : g_k) + (size_t)s * DIM;
    const float* w = isq ? nqw : nkw;
    __nv_bfloat16* outh = isq ? g_qbh : g_kbh;
    __nv_bfloat16* outl = isq ? g_qbl : g_kbl;
    float oscale = isq ? 0.08838834764831845f : 1.0f;

    __shared__ float row[DIM];
    __shared__ float red[8];

    int tid = threadIdx.x;
    float ss = 0.f;
    for (int i = tid; i < DIM; i += 256) {
        float v = buf[i];
        row[i] = v;
        ss += v * v;
    }
#pragma unroll
    for (int o = 16; o; o >>= 1) ss += __shfl_xor_sync(0xffffffff, ss, o);
    if ((tid & 31) == 0) red[tid >> 5] = ss;
    __syncthreads();
    if (tid < 8) {
        float t = red[tid];
#pragma unroll
        for (int o = 4; o; o >>= 1) t += __shfl_xor_sync(0xff, t, o);
        if (tid == 0) red[0] = t;
    }
    __syncthreads();
    float r = rsqrtf(red[0] / (float)DIM + 1e-6f);

    int fi = s / (HG * WG);
    int rem = s % (HG * WG);
    int hi = rem / WG;
    int wi = rem % WG;

    for (int p = tid; p < NH * 64; p += 256) {
        int h = p >> 6, c = p & 63;
        int pos = (c < D_F) ? fi : (c < D_FH) ? hi : wi;
        float ang = freqs[pos * 64 + c];
        float sn, cs;
        sincosf(ang, &sn, &cs);
        int j = h * HD + 2 * c;
        float y0 = row[j] * r * w[j];
        float y1 = row[j + 1] * r * w[j + 1];
        float v0 = (y0 * cs - y1 * sn) * oscale;
        float v1 = (y0 * sn + y1 * cs) * oscale;
        __nv_bfloat162 hh = __float22bfloat162_rn(make_float2(v0, v1));
        float r0 = v0 - __bfloat162float(hh.x);
        float r1 = v1 - __bfloat162float(hh.y);
        __nv_bfloat162 ll = __float22bfloat162_rn(make_float2(r0, r1));
        size_t off = ((size_t)h * SEQ + s) * HD + 2 * c;
        *(__nv_bfloat162*)&outh[off] = hh;
        *(__nv_bfloat162*)&outl[off] = ll;
    }
}

// ---------------- tensor-core flash attention (bf16x3) -------------------------
// grid (SEQ/128, NH), 256 thr. warp w -> q rows [16w,16w+16). kv step 64.
#define KROWB   272            // K/Q smem row bytes (128 bf16 + pad)
#define KROWW   68             // words
#define VROWB   144            // Vt smem row bytes (64 bf16 + pad)
#define VROWW   36
#define SZKB    (64 * KROWB)   // 17408 B per K buffer
#define SZVB    (128 * VROWB)  // 18432 B per Vt buffer
#define STAGEB  (2 * SZKB + 2 * SZVB)   // 71680
#define ATT_SMEM (2 * STAGEB)           // 143360
#define NKB     (SEQ / 64)

__global__ __launch_bounds__(256, 1)
void attn_tc()
{
    extern __shared__ char smem[];
    uint32_t sbase = smem_u32(smem);
    uint32_t* sw = (uint32_t*)smem;

    int tid = threadIdx.x, wid = tid >> 5, lid = tid & 31;
    int g = lid >> 2, tg = lid & 3;
    int h = blockIdx.y;
    int q0 = blockIdx.x * 128;

    // ---- stage Q (hi at bytes [0,34816), lo at [34816,69632)) ----
#pragma unroll
    for (int i = 0; i < 8; i++) {
        int idx = tid + i * 256;
        int r = idx >> 4, sc = idx & 15;
        size_t gsrc = (((size_t)h * SEQ + q0 + r) * HD) * 2 + sc * 16;
        cpasync16(sbase + r * KROWB + sc * 16, (const char*)g_qbh + gsrc);
        cpasync16(sbase + 34816 + r * KROWB + sc * 16, (const char*)g_qbl + gsrc);
    }
    CP_COMMIT();
    CP_WAIT0();
    __syncthreads();

    // ---- Q fragments to registers ----
    uint32_t qh[8][4], ql[8][4];
    int rw = wid * 16;
#pragma unroll
    for (int kt = 0; kt < 8; kt++) {
        int base = (rw + g) * KROWW + 8 * kt + tg;
        int base8 = (rw + g + 8) * KROWW + 8 * kt + tg;
        qh[kt][0] = sw[base];
        qh[kt][1] = sw[base8];
        qh[kt][2] = sw[base + 4];
        qh[kt][3] = sw[base8 + 4];
        ql[kt][0] = sw[8704 + base];
        ql[kt][1] = sw[8704 + base8];
        ql[kt][2] = sw[8704 + base + 4];
        ql[kt][3] = sw[8704 + base8 + 4];
    }
    __syncthreads();   // Q regs extracted; smem can be reused for stages

    float o[16][4];
#pragma unroll
    for (int nt = 0; nt < 16; nt++)
#pragma unroll
        for (int c = 0; c < 4; c++) o[nt][c] = 0.f;
    float m0 = -1e30f, m1 = -1e30f, l0 = 0.f, l1 = 0.f;

    // ---- pipeline issue lambda ----
    auto issue = [&](int kb, int s) {
        int k0 = kb * 64;
        uint32_t sb = sbase + s * STAGEB;
#pragma unroll
        for (int i = 0; i < 4; i++) {
            int idx = tid + i * 256;
            int r = idx >> 4, sc = idx & 15;
            size_t gk = (((size_t)h * SEQ + k0 + r) * HD) * 2 + sc * 16;
            cpasync16(sb + r * KROWB + sc * 16, (const char*)g_kbh + gk);
            cpasync16(sb + SZKB + r * KROWB + sc * 16, (const char*)g_kbl + gk);
        }
#pragma unroll
        for (int i = 0; i < 4; i++) {
            int idx = tid + i * 256;
            int d = idx >> 3, sc = idx & 7;
            size_t gv = (((size_t)h * HD + d) * SEQ + k0) * 2 + sc * 16;
            cpasync16(sb + 2 * SZKB + d * VROWB + sc * 16, (const char*)g_vth + gv);
            cpasync16(sb + 2 * SZKB + SZVB + d * VROWB + sc * 16,
                      (const char*)g_vtl + gv);
        }
    };

    issue(0, 0); CP_COMMIT();
    issue(1, 1); CP_COMMIT();

    for (int kb = 0; kb < NKB; kb++) {
        int s = kb & 1;
        CP_WAIT1();
        __syncthreads();

        uint32_t SK = s * (STAGEB / 4);          // stage base, words
        uint32_t SKl = SK + SZKB / 4;
        uint32_t SV = SK + 2 * (SZKB / 4);
        uint32_t SVl = SV + SZVB / 4;

        // ---- S = Q K^T (bf16x3) ----
        float sacc[8][4];
#pragma unroll
        for (int nt = 0; nt < 8; nt++)
#pragma unroll
            for (int c = 0; c < 4; c++) sacc[nt][c] = 0.f;

#pragma unroll
        for (int kt = 0; kt < 8; kt++) {
#pragma unroll
            for (int nt = 0; nt < 8; nt++) {
                int bo = (8 * nt + g) * KROWW + 8 * kt + tg;
                uint32_t bh0 = sw[SK + bo], bh1 = sw[SK + bo + 4];
                uint32_t bl0 = sw[SKl + bo], bl1 = sw[SKl + bo + 4];
                mma16816(sacc[nt][0], sacc[nt][1], sacc[nt][2], sacc[nt][3],
                         qh[kt][0], qh[kt][1], qh[kt][2], qh[kt][3], bh0, bh1);
                mma16816(sacc[nt][0], sacc[nt][1], sacc[nt][2], sacc[nt][3],
                         ql[kt][0], ql[kt][1], ql[kt][2], ql[kt][3], bh0, bh1);
                mma16816(sacc[nt][0], sacc[nt][1], sacc[nt][2], sacc[nt][3],
                         qh[kt][0], qh[kt][1], qh[kt][2], qh[kt][3], bl0, bl1);
            }
        }

        // ---- online softmax (rows g and g+8; quad-local reductions) ----
        float mx0 = -1e30f, mx1 = -1e30f;
#pragma unroll
        for (int nt = 0; nt < 8; nt++) {
            mx0 = fmaxf(mx0, fmaxf(sacc[nt][0], sacc[nt][1]));
            mx1 = fmaxf(mx1, fmaxf(sacc[nt][2], sacc[nt][3]));
        }
        mx0 = fmaxf(mx0, __shfl_xor_sync(0xffffffffu, mx0, 1));
        mx0 = fmaxf(mx0, __shfl_xor_sync(0xffffffffu, mx0, 2));
        mx1 = fmaxf(mx1, __shfl_xor_sync(0xffffffffu, mx1, 1));
        mx1 = fmaxf(mx1, __shfl_xor_sync(0xffffffffu, mx1, 2));
        float mn0 = fmaxf(m0, mx0), mn1 = fmaxf(m1, mx1);
        float corr0 = __expf(m0 - mn0), corr1 = __expf(m1 - mn1);
        m0 = mn0; m1 = mn1;
        float ls0 = 0.f, ls1 = 0.f;
#pragma unroll
        for (int nt = 0; nt < 8; nt++) {
            sacc[nt][0] = __expf(sacc[nt][0] - m0); ls0 += sacc[nt][0];
            sacc[nt][1] = __expf(sacc[nt][1] - m0); ls0 += sacc[nt][1];
            sacc[nt][2] = __expf(sacc[nt][2] - m1); ls1 += sacc[nt][2];
            sacc[nt][3] = __expf(sacc[nt][3] - m1); ls1 += sacc[nt][3];
        }
        ls0 += __shfl_xor_sync(0xffffffffu, ls0, 1);
        ls0 += __shfl_xor_sync(0xffffffffu, ls0, 2);
        ls1 += __shfl_xor_sync(0xffffffffu, ls1, 1);
        ls1 += __shfl_xor_sync(0xffffffffu, ls1, 2);
        l0 = l0 * corr0 + ls0;
        l1 = l1 * corr1 + ls1;

        // ---- rescale O ----
#pragma unroll
        for (int nt = 0; nt < 16; nt++) {
            o[nt][0] *= corr0; o[nt][1] *= corr0;
            o[nt][2] *= corr1; o[nt][3] *= corr1;
        }

        // ---- O += P V (bf16x3); P frags repacked from sacc ----
#pragma unroll
        for (int kt = 0; kt < 4; kt++) {
            uint32_t pah[4], pal[4];
#pragma unroll
            for (int half = 0; half < 2; half++) {
                int nt2 = 2 * kt + half;
                __nv_bfloat162 h0 = __float22bfloat162_rn(
                    make_float2(sacc[nt2][0], sacc[nt2][1]));
                __nv_bfloat162 l0p = __float22bfloat162_rn(
                    make_float2(sacc[nt2][0] - __bfloat162float(h0.x),
                                sacc[nt2][1] - __bfloat162float(h0.y)));
                __nv_bfloat162 h1 = __float22bfloat162_rn(
                    make_float2(sacc[nt2][2], sacc[nt2][3]));
                __nv_bfloat162 l1p = __float22bfloat162_rn(
                    make_float2(sacc[nt2][2] - __bfloat162float(h1.x),
                                sacc[nt2][3] - __bfloat162float(h1.y)));
                pah[half * 2 + 0] = *(uint32_t*)&h0;
                pah[half * 2 + 1] = *(uint32_t*)&h1;
                pal[half * 2 + 0] = *(uint32_t*)&l0p;
                pal[half * 2 + 1] = *(uint32_t*)&l1p;
            }
#pragma unroll
            for (int nt = 0; nt < 16; nt++) {
                int bo = (8 * nt + g) * VROWW + 8 * kt + tg;
                uint32_t bh0 = sw[SV + bo], bh1 = sw[SV + bo + 4];
                uint32_t bl0 = sw[SVl + bo], bl1 = sw[SVl + bo + 4];
                mma16816(o[nt][0], o[nt][1], o[nt][2], o[nt][3],
                         pah[0], pah[1], pah[2], pah[3], bh0, bh1);
                mma16816(o[nt][0], o[nt][1], o[nt][2], o[nt][3],
                         pal[0], pal[1], pal[2], pal[3], bh0, bh1);
                mma16816(o[nt][0], o[nt][1], o[nt][2], o[nt][3],
                         pah[0], pah[1], pah[2], pah[3], bl0, bl1);
            }
        }

        __syncthreads();
        if (kb + 2 < NKB) issue(kb + 2, s);
        CP_COMMIT();
    }

    // ---- normalize + store ----
    float inv0 = 1.0f / l0, inv1 = 1.0f / l1;
    int row = q0 + rw + g;
#pragma unroll
    for (int nt = 0; nt < 16; nt++) {
        int col = h * HD + 8 * nt + 2 * tg;
        *(float2*)&g_att[(size_t)row * DIM + col] =
            make_float2(o[nt][0] * inv0, o[nt][1] * inv0);
        *(float2*)&g_att[(size_t)(row + 8) * DIM + col] =
            make_float2(o[nt][2] * inv1, o[nt][3] * inv1);
    }
}

// ---------------- launch ------------------------------------------------------
extern "C" void kernel_launch(void* const* d_in, const int* in_sizes, int n_in,
                              void* d_out, int out_size)
{
    const float* x    = (const float*)d_in[0];
    const float* q_w  = (const float*)d_in[1];
    const float* q_b  = (const float*)d_in[2];
    const float* k_w  = (const float*)d_in[3];
    const float* k_b  = (const float*)d_in[4];
    const float* v_w  = (const float*)d_in[5];
    const float* v_b  = (const float*)d_in[6];
    const float* o_w  = (const float*)d_in[7];
    const float* o_b  = (const float*)d_in[8];
    const float* nqw  = (const float*)d_in[9];
    const float* nkw  = (const float*)d_in[10];
    const float* freqs = (const float*)d_in[11];
    float* out = (float*)d_out;

    cudaFuncSetAttribute(attn_tc, cudaFuncAttributeMaxDynamicSharedMemorySize,
                         ATT_SMEM);

    split_act<<<SEQ * DIM / 1024, 256>>>(x, 0);
    transpose_split<<<dim3(DIM / 32, DIM / 32, 4), dim3(32, 8)>>>(q_w, k_w, v_w, o_w);

    dim3 gg(DIM / 128, SEQ / 128);
    hgemm<<<gg, 256>>>(0, 0, q_b, nullptr, 0);
    hgemm<<<gg, 256>>>(0, 1, k_b, nullptr, 1);
    hgemm<<<gg, 256>>>(0, 2, v_b, nullptr, 2);

    normrope_kernel<<<dim3(SEQ, 2), 256>>>(nqw, nkw, freqs);
    transpose_v<<<dim3(SEQ / 32, HD / 32, NH), dim3(32, 8)>>>();

    attn_tc<<<dim3(SEQ / 128, NH), 256, ATT_SMEM>>>();

    split_act<<<SEQ * DIM / 1024, 256>>>(nullptr, 1);
    hgemm<<<gg, 256>>>(1, 3, o_b, out, 3);
}

// round 8
// speedup vs baseline: 2.0534x; 1.0768x over previous
#include <cuda_runtime.h>
#include <cuda_bf16.h>
#include <math.h>
#include <stdint.h>

#define SEQ   3840
#define DIM   1536
#define NH    12
#define HD    128
#define HG    20
#define WG    24
#define D_F   22
#define D_FH  43

typedef unsigned long long u64;

// ---------------- scratch (device globals; no runtime allocation) -------------
__device__ float g_q[SEQ * DIM];
__device__ float g_k[SEQ * DIM];
__device__ float g_v[SEQ * DIM];
__device__ float g_att[SEQ * DIM];

__device__ __nv_bfloat16 g_xh[SEQ * DIM], g_xl[SEQ * DIM];       // x split
__device__ __nv_bfloat16 g_ah[SEQ * DIM], g_al[SEQ * DIM];       // att split
__device__ __nv_bfloat16 g_wh[4][DIM * DIM], g_wl[4][DIM * DIM]; // W^T splits

// attention operands, head-major bf16 hi/lo
__device__ __nv_bfloat16 g_qbh[NH * SEQ * HD], g_qbl[NH * SEQ * HD]; // [h][s][d]
__device__ __nv_bfloat16 g_kbh[NH * SEQ * HD], g_kbl[NH * SEQ * HD]; // [h][s][d]
__device__ __nv_bfloat16 g_vth[NH * HD * SEQ], g_vtl[NH * HD * SEQ]; // [h][d][s]

// ---------------- helpers -----------------------------------------------------
__device__ __forceinline__ uint32_t smem_u32(const void* p) {
    uint32_t a;
    asm("{ .reg .u64 t; cvta.to.shared.u64 t, %1; cvt.u32.u64 %0, t; }"
        : "=r"(a) : "l"(p));
    return a;
}
__device__ __forceinline__ void cpasync16(uint32_t saddr, const void* g) {
    asm volatile("cp.async.cg.shared.global [%0], [%1], 16;"
                 :: "r"(saddr), "l"(g) : "memory");
}
#define CP_COMMIT() asm volatile("cp.async.commit_group;" ::: "memory")
#define CP_WAIT0()  asm volatile("cp.async.wait_group 0;" ::: "memory")
#define CP_WAIT1()  asm volatile("cp.async.wait_group 1;" ::: "memory")

__device__ __forceinline__ void mma16816(float& d0, float& d1, float& d2, float& d3,
                                         uint32_t a0, uint32_t a1, uint32_t a2,
                                         uint32_t a3, uint32_t b0, uint32_t b1) {
    asm volatile(
        "mma.sync.aligned.m16n8k16.row.col.f32.bf16.bf16.f32 "
        "{%0,%1,%2,%3}, {%4,%5,%6,%7}, {%8,%9}, {%0,%1,%2,%3};"
        : "+f"(d0), "+f"(d1), "+f"(d2), "+f"(d3)
        : "r"(a0), "r"(a1), "r"(a2), "r"(a3), "r"(b0), "r"(b1));
}

// ---------------- prep: split activations into bf16 hi/lo ---------------------
__global__ void split_act(const float* __restrict__ xsrc, int which)
{
    const float* src = (which == 0) ? xsrc : g_att;
    __nv_bfloat16* dh = (which == 0) ? g_xh : g_ah;
    __nv_bfloat16* dl = (which == 0) ? g_xl : g_al;
    int i = (blockIdx.x * 256 + threadIdx.x) * 4;
    float4 v = *(const float4*)&src[i];
    __nv_bfloat16 h0 = __float2bfloat16(v.x), h1 = __float2bfloat16(v.y);
    __nv_bfloat16 h2 = __float2bfloat16(v.z), h3 = __float2bfloat16(v.w);
    __nv_bfloat16 l0 = __float2bfloat16(v.x - __bfloat162float(h0));
    __nv_bfloat16 l1 = __float2bfloat16(v.y - __bfloat162float(h1));
    __nv_bfloat16 l2 = __float2bfloat16(v.z - __bfloat162float(h2));
    __nv_bfloat16 l3 = __float2bfloat16(v.w - __bfloat162float(h3));
    ushort4 hh, ll;
    hh.x = *(unsigned short*)&h0; hh.y = *(unsigned short*)&h1;
    hh.z = *(unsigned short*)&h2; hh.w = *(unsigned short*)&h3;
    ll.x = *(unsigned short*)&l0; ll.y = *(unsigned short*)&l1;
    ll.z = *(unsigned short*)&l2; ll.w = *(unsigned short*)&l3;
    *(ushort4*)&dh[i] = hh;
    *(ushort4*)&dl[i] = ll;
}

// ---------------- prep: transpose + split weights ------------------------------
__global__ void transpose_split(const float* __restrict__ w0,
                                const float* __restrict__ w1,
                                const float* __restrict__ w2,
                                const float* __restrict__ w3)
{
    const float* W = (blockIdx.z == 0) ? w0 : (blockIdx.z == 1) ? w1
                   : (blockIdx.z == 2) ? w2 : w3;
    __nv_bfloat16* Oh = g_wh[blockIdx.z];
    __nv_bfloat16* Ol = g_wl[blockIdx.z];

    __shared__ float t[32][33];
    int k0 = blockIdx.y * 32, n0 = blockIdx.x * 32;
    int tx = threadIdx.x, ty = threadIdx.y;
#pragma unroll
    for (int j = 0; j < 4; j++)
        t[ty + j * 8][tx] = W[(size_t)(k0 + ty + j * 8) * DIM + n0 + tx];
    __syncthreads();
#pragma unroll
    for (int j = 0; j < 4; j++) {
        float v = t[tx][ty + j * 8];
        __nv_bfloat16 h = __float2bfloat16(v);
        __nv_bfloat16 l = __float2bfloat16(v - __bfloat162float(h));
        size_t o = (size_t)(n0 + ty + j * 8) * DIM + k0 + tx;
        Oh[o] = h;
        Ol[o] = l;
    }
}

// ---------------- prep: transpose V to [h][d][s] bf16 hi/lo --------------------
__global__ void transpose_v()
{
    __shared__ float t[32][33];
    int s0 = blockIdx.x * 32, d0 = blockIdx.y * 32, h = blockIdx.z;
    int tx = threadIdx.x, ty = threadIdx.y;
#pragma unroll
    for (int j = 0; j < 4; j++)
        t[ty + j * 8][tx] = g_v[(size_t)(s0 + ty + j * 8) * DIM + h * HD + d0 + tx];
    __syncthreads();
#pragma unroll
    for (int j = 0; j < 4; j++) {
        float v = t[tx][ty + j * 8];
        __nv_bfloat16 hb = __float2bfloat16(v);
        __nv_bfloat16 lb = __float2bfloat16(v - __bfloat162float(hb));
        size_t o = ((size_t)h * HD + d0 + ty + j * 8) * SEQ + s0 + tx;
        g_vth[o] = hb;
        g_vtl[o] = lb;
    }
}

// ---------------- mma.sync bf16x3 GEMM, double-buffered ------------------------
// C[3840,1536] = A @ W^T(stored [N][K]) + bias. 128x128 CTA tile, BK=32.
// gridDim.z selects weight wbase+z. 2-stage cp.async pipeline, dyn smem 80KB.
#define TS 40
#define TILEB (128 * TS * 2)            // 10240 B per tile
#define GSTAGE (4 * TILEB)              // 40960 B per stage
#define HG_SMEM (2 * GSTAGE)            // 81920 B
#define NCH (DIM / 32)                  // 48 chunks

__global__ __launch_bounds__(256, 2)
void hgemm(int asel, int wbase,
           const float* __restrict__ b0, const float* __restrict__ b1,
           const float* __restrict__ b2, const float* __restrict__ b3,
           float* __restrict__ Cout)
{
    extern __shared__ char hsm[];
    int wsel = wbase + blockIdx.z;
    const __nv_bfloat16* Agh = asel ? g_ah : g_xh;
    const __nv_bfloat16* Agl = asel ? g_al : g_xl;
    const __nv_bfloat16* Bgh = g_wh[wsel];
    const __nv_bfloat16* Bgl = g_wl[wsel];
    const float* bias = (wsel == 0) ? b0 : (wsel == 1) ? b1 : (wsel == 2) ? b2 : b3;
    float* C = (wsel == 0) ? g_q : (wsel == 1) ? g_k : (wsel == 2) ? g_v : Cout;

    uint32_t sbase = smem_u32(hsm);

    int tid = threadIdx.x, wid = tid >> 5, lid = tid & 31;
    int wm = wid >> 2, wn = wid & 3;
    int g = lid >> 2, tg = lid & 3;
    int m0 = blockIdx.y * 128, n0 = blockIdx.x * 128;

    int r0 = tid >> 2, sc0 = tid & 3;
    int r1 = (tid + 256) >> 2;
    uint32_t so0 = r0 * (TS * 2) + sc0 * 16;
    uint32_t so1 = r1 * (TS * 2) + sc0 * 16;

    float acc[4][4][4];
#pragma unroll
    for (int t = 0; t < 4; t++)
#pragma unroll
        for (int u = 0; u < 4; u++)
#pragma unroll
            for (int c = 0; c < 4; c++) acc[t][u][c] = 0.f;

    auto issue = [&](int ch, int s) {
        uint32_t sb = sbase + s * GSTAGE;
        size_t ga0 = (size_t)(m0 + r0) * DIM + ch * 32 + sc0 * 8;
        size_t ga1 = (size_t)(m0 + r1) * DIM + ch * 32 + sc0 * 8;
        size_t gb0 = (size_t)(n0 + r0) * DIM + ch * 32 + sc0 * 8;
        size_t gb1 = (size_t)(n0 + r1) * DIM + ch * 32 + sc0 * 8;
        cpasync16(sb + so0, &Agh[ga0]);
        cpasync16(sb + so1, &Agh[ga1]);
        cpasync16(sb + TILEB + so0, &Agl[ga0]);
        cpasync16(sb + TILEB + so1, &Agl[ga1]);
        cpasync16(sb + 2 * TILEB + so0, &Bgh[gb0]);
        cpasync16(sb + 2 * TILEB + so1, &Bgh[gb1]);
        cpasync16(sb + 3 * TILEB + so0, &Bgl[gb0]);
        cpasync16(sb + 3 * TILEB + so1, &Bgl[gb1]);
    };

    issue(0, 0); CP_COMMIT();
    issue(1, 1); CP_COMMIT();

    for (int ch = 0; ch < NCH; ch++) {
        int s = ch & 1;
        CP_WAIT1();
        __syncthreads();

        const __nv_bfloat16* sAh = (const __nv_bfloat16*)(hsm + s * GSTAGE);
        const __nv_bfloat16* sAl = sAh + 128 * TS;
        const __nv_bfloat16* sBh = sAh + 2 * 128 * TS;
        const __nv_bfloat16* sBl = sAh + 3 * 128 * TS;

#pragma unroll
        for (int ks = 0; ks < 2; ks++) {
            int kc = ks * 16 + tg * 2;
            uint32_t ah[4][4], bh[4][2];
#pragma unroll
            for (int t = 0; t < 4; t++) {
                int ra = wm * 64 + t * 16 + g;
                ah[t][0] = *(uint32_t*)&sAh[ra * TS + kc];
                ah[t][1] = *(uint32_t*)&sAh[(ra + 8) * TS + kc];
                ah[t][2] = *(uint32_t*)&sAh[ra * TS + kc + 8];
                ah[t][3] = *(uint32_t*)&sAh[(ra + 8) * TS + kc + 8];
            }
#pragma unroll
            for (int u = 0; u < 4; u++) {
                int rb = wn * 32 + u * 8 + g;
                bh[u][0] = *(uint32_t*)&sBh[rb * TS + kc];
                bh[u][1] = *(uint32_t*)&sBh[rb * TS + kc + 8];
            }
#pragma unroll
            for (int t = 0; t < 4; t++)
#pragma unroll
                for (int u = 0; u < 4; u++)
                    mma16816(acc[t][u][0], acc[t][u][1], acc[t][u][2], acc[t][u][3],
                             ah[t][0], ah[t][1], ah[t][2], ah[t][3],
                             bh[u][0], bh[u][1]);
#pragma unroll
            for (int u = 0; u < 4; u++) {
                int rb = wn * 32 + u * 8 + g;
                uint32_t bl0 = *(uint32_t*)&sBl[rb * TS + kc];
                uint32_t bl1 = *(uint32_t*)&sBl[rb * TS + kc + 8];
#pragma unroll
                for (int t = 0; t < 4; t++)
                    mma16816(acc[t][u][0], acc[t][u][1], acc[t][u][2], acc[t][u][3],
                             ah[t][0], ah[t][1], ah[t][2], ah[t][3], bl0, bl1);
            }
#pragma unroll
            for (int t = 0; t < 4; t++) {
                int ra = wm * 64 + t * 16 + g;
                uint32_t al0 = *(uint32_t*)&sAl[ra * TS + kc];
                uint32_t al1 = *(uint32_t*)&sAl[(ra + 8) * TS + kc];
                uint32_t al2 = *(uint32_t*)&sAl[ra * TS + kc + 8];
                uint32_t al3 = *(uint32_t*)&sAl[(ra + 8) * TS + kc + 8];
#pragma unroll
                for (int u = 0; u < 4; u++)
                    mma16816(acc[t][u][0], acc[t][u][1], acc[t][u][2], acc[t][u][3],
                             al0, al1, al2, al3, bh[u][0], bh[u][1]);
            }
        }
        __syncthreads();
        if (ch + 2 < NCH) issue(ch + 2, s);
        CP_COMMIT();
    }

#pragma unroll
    for (int t = 0; t < 4; t++) {
        int row = m0 + wm * 64 + t * 16 + g;
#pragma unroll
        for (int u = 0; u < 4; u++) {
            int col = n0 + wn * 32 + u * 8 + tg * 2;
            float2 bv = *(const float2*)&bias[col];
            float2 lo = make_float2(acc[t][u][0] + bv.x, acc[t][u][1] + bv.y);
            float2 hi = make_float2(acc[t][u][2] + bv.x, acc[t][u][3] + bv.y);
            *(float2*)&C[(size_t)row * DIM + col] = lo;
            *(float2*)&C[(size_t)(row + 8) * DIM + col] = hi;
        }
    }
}

// ---------------- RMSNorm + RoPE -> bf16 hi/lo head-major ----------------------
__global__ void normrope_kernel(const float* __restrict__ nqw,
                                const float* __restrict__ nkw,
                                const float* __restrict__ freqs)
{
    int s = blockIdx.x;
    bool isq = (blockIdx.y == 0);
    const float* buf = (isq ? g_q : g_k) + (size_t)s * DIM;
    const float* w = isq ? nqw : nkw;
    __nv_bfloat16* outh = isq ? g_qbh : g_kbh;
    __nv_bfloat16* outl = isq ? g_qbl : g_kbl;
    float oscale = isq ? 0.08838834764831845f : 1.0f;

    __shared__ float row[DIM];
    __shared__ float red[8];

    int tid = threadIdx.x;
    float ss = 0.f;
    for (int i = tid; i < DIM; i += 256) {
        float v = buf[i];
        row[i] = v;
        ss += v * v;
    }
#pragma unroll
    for (int o = 16; o; o >>= 1) ss += __shfl_xor_sync(0xffffffff, ss, o);
    if ((tid & 31) == 0) red[tid >> 5] = ss;
    __syncthreads();
    if (tid < 8) {
        float t = red[tid];
#pragma unroll
        for (int o = 4; o; o >>= 1) t += __shfl_xor_sync(0xff, t, o);
        if (tid == 0) red[0] = t;
    }
    __syncthreads();
    float r = rsqrtf(red[0] / (float)DIM + 1e-6f);

    int fi = s / (HG * WG);
    int rem = s % (HG * WG);
    int hi = rem / WG;
    int wi = rem % WG;

    for (int p = tid; p < NH * 64; p += 256) {
        int h = p >> 6, c = p & 63;
        int pos = (c < D_F) ? fi : (c < D_FH) ? hi : wi;
        float ang = freqs[pos * 64 + c];
        float sn, cs;
        sincosf(ang, &sn, &cs);
        int j = h * HD + 2 * c;
        float y0 = row[j] * r * w[j];
        float y1 = row[j + 1] * r * w[j + 1];
        float v0 = (y0 * cs - y1 * sn) * oscale;
        float v1 = (y0 * sn + y1 * cs) * oscale;
        __nv_bfloat162 hh = __float22bfloat162_rn(make_float2(v0, v1));
        float r0 = v0 - __bfloat162float(hh.x);
        float r1 = v1 - __bfloat162float(hh.y);
        __nv_bfloat162 ll = __float22bfloat162_rn(make_float2(r0, r1));
        size_t off = ((size_t)h * SEQ + s) * HD + 2 * c;
        *(__nv_bfloat162*)&outh[off] = hh;
        *(__nv_bfloat162*)&outl[off] = ll;
    }
}

// ---------------- tensor-core flash attention (bf16x3) -------------------------
#define KROWB   272
#define KROWW   68
#define VROWB   144
#define VROWW   36
#define SZKB    (64 * KROWB)
#define SZVB    (128 * VROWB)
#define STAGEB  (2 * SZKB + 2 * SZVB)
#define ATT_SMEM (2 * STAGEB)
#define NKB     (SEQ / 64)

__global__ __launch_bounds__(256, 1)
void attn_tc()
{
    extern __shared__ char smem[];
    uint32_t sbase = smem_u32(smem);
    uint32_t* sw = (uint32_t*)smem;

    int tid = threadIdx.x, wid = tid >> 5, lid = tid & 31;
    int g = lid >> 2, tg = lid & 3;
    int h = blockIdx.y;
    int q0 = blockIdx.x * 128;

#pragma unroll
    for (int i = 0; i < 8; i++) {
        int idx = tid + i * 256;
        int r = idx >> 4, sc = idx & 15;
        size_t gsrc = (((size_t)h * SEQ + q0 + r) * HD) * 2 + sc * 16;
        cpasync16(sbase + r * KROWB + sc * 16, (const char*)g_qbh + gsrc);
        cpasync16(sbase + 34816 + r * KROWB + sc * 16, (const char*)g_qbl + gsrc);
    }
    CP_COMMIT();
    CP_WAIT0();
    __syncthreads();

    uint32_t qh[8][4], ql[8][4];
    int rw = wid * 16;
#pragma unroll
    for (int kt = 0; kt < 8; kt++) {
        int base = (rw + g) * KROWW + 8 * kt + tg;
        int base8 = (rw + g + 8) * KROWW + 8 * kt + tg;
        qh[kt][0] = sw[base];
        qh[kt][1] = sw[base8];
        qh[kt][2] = sw[base + 4];
        qh[kt][3] = sw[base8 + 4];
        ql[kt][0] = sw[8704 + base];
        ql[kt][1] = sw[8704 + base8];
        ql[kt][2] = sw[8704 + base + 4];
        ql[kt][3] = sw[8704 + base8 + 4];
    }
    __syncthreads();

    float o[16][4];
#pragma unroll
    for (int nt = 0; nt < 16; nt++)
#pragma unroll
        for (int c = 0; c < 4; c++) o[nt][c] = 0.f;
    float m0 = -1e30f, m1 = -1e30f, l0 = 0.f, l1 = 0.f;

    auto issue = [&](int kb, int s) {
        int k0 = kb * 64;
        uint32_t sb = sbase + s * STAGEB;
#pragma unroll
        for (int i = 0; i < 4; i++) {
            int idx = tid + i * 256;
            int r = idx >> 4, sc = idx & 15;
            size_t gk = (((size_t)h * SEQ + k0 + r) * HD) * 2 + sc * 16;
            cpasync16(sb + r * KROWB + sc * 16, (const char*)g_kbh + gk);
            cpasync16(sb + SZKB + r * KROWB + sc * 16, (const char*)g_kbl + gk);
        }
#pragma unroll
        for (int i = 0; i < 4; i++) {
            int idx = tid + i * 256;
            int d = idx >> 3, sc = idx & 7;
            size_t gv = (((size_t)h * HD + d) * SEQ + k0) * 2 + sc * 16;
            cpasync16(sb + 2 * SZKB + d * VROWB + sc * 16, (const char*)g_vth + gv);
            cpasync16(sb + 2 * SZKB + SZVB + d * VROWB + sc * 16,
                      (const char*)g_vtl + gv);
        }
    };

    issue(0, 0); CP_COMMIT();
    issue(1, 1); CP_COMMIT();

    for (int kb = 0; kb < NKB; kb++) {
        int s = kb & 1;
        CP_WAIT1();
        __syncthreads();

        uint32_t SK = s * (STAGEB / 4);
        uint32_t SKl = SK + SZKB / 4;
        uint32_t SV = SK + 2 * (SZKB / 4);
        uint32_t SVl = SV + SZVB / 4;

        float sacc[8][4];
#pragma unroll
        for (int nt = 0; nt < 8; nt++)
#pragma unroll
            for (int c = 0; c < 4; c++) sacc[nt][c] = 0.f;

#pragma unroll
        for (int kt = 0; kt < 8; kt++) {
#pragma unroll
            for (int nt = 0; nt < 8; nt++) {
                int bo = (8 * nt + g) * KROWW + 8 * kt + tg;
                uint32_t bh0 = sw[SK + bo], bh1 = sw[SK + bo + 4];
                uint32_t bl0 = sw[SKl + bo], bl1 = sw[SKl + bo + 4];
                mma16816(sacc[nt][0], sacc[nt][1], sacc[nt][2], sacc[nt][3],
                         qh[kt][0], qh[kt][1], qh[kt][2], qh[kt][3], bh0, bh1);
                mma16816(sacc[nt][0], sacc[nt][1], sacc[nt][2], sacc[nt][3],
                         ql[kt][0], ql[kt][1], ql[kt][2], ql[kt][3], bh0, bh1);
                mma16816(sacc[nt][0], sacc[nt][1], sacc[nt][2], sacc[nt][3],
                         qh[kt][0], qh[kt][1], qh[kt][2], qh[kt][3], bl0, bl1);
            }
        }

        float mx0 = -1e30f, mx1 = -1e30f;
#pragma unroll
        for (int nt = 0; nt < 8; nt++) {
            mx0 = fmaxf(mx0, fmaxf(sacc[nt][0], sacc[nt][1]));
            mx1 = fmaxf(mx1, fmaxf(sacc[nt][2], sacc[nt][3]));
        }
        mx0 = fmaxf(mx0, __shfl_xor_sync(0xffffffffu, mx0, 1));
        mx0 = fmaxf(mx0, __shfl_xor_sync(0xffffffffu, mx0, 2));
        mx1 = fmaxf(mx1, __shfl_xor_sync(0xffffffffu, mx1, 1));
        mx1 = fmaxf(mx1, __shfl_xor_sync(0xffffffffu, mx1, 2));
        float mn0 = fmaxf(m0, mx0), mn1 = fmaxf(m1, mx1);
        float corr0 = __expf(m0 - mn0), corr1 = __expf(m1 - mn1);
        m0 = mn0; m1 = mn1;
        float ls0 = 0.f, ls1 = 0.f;
#pragma unroll
        for (int nt = 0; nt < 8; nt++) {
            sacc[nt][0] = __expf(sacc[nt][0] - m0); ls0 += sacc[nt][0];
            sacc[nt][1] = __expf(sacc[nt][1] - m0); ls0 += sacc[nt][1];
            sacc[nt][2] = __expf(sacc[nt][2] - m1); ls1 += sacc[nt][2];
            sacc[nt][3] = __expf(sacc[nt][3] - m1); ls1 += sacc[nt][3];
        }
        ls0 += __shfl_xor_sync(0xffffffffu, ls0, 1);
        ls0 += __shfl_xor_sync(0xffffffffu, ls0, 2);
        ls1 += __shfl_xor_sync(0xffffffffu, ls1, 1);
        ls1 += __shfl_xor_sync(0xffffffffu, ls1, 2);
        l0 = l0 * corr0 + ls0;
        l1 = l1 * corr1 + ls1;

#pragma unroll
        for (int nt = 0; nt < 16; nt++) {
            o[nt][0] *= corr0; o[nt][1] *= corr0;
            o[nt][2] *= corr1; o[nt][3] *= corr1;
        }

#pragma unroll
        for (int kt = 0; kt < 4; kt++) {
            uint32_t pah[4], pal[4];
#pragma unroll
            for (int half = 0; half < 2; half++) {
                int nt2 = 2 * kt + half;
                __nv_bfloat162 h0 = __float22bfloat162_rn(
                    make_float2(sacc[nt2][0], sacc[nt2][1]));
                __nv_bfloat162 l0p = __float22bfloat162_rn(
                    make_float2(sacc[nt2][0] - __bfloat162float(h0.x),
                                sacc[nt2][1] - __bfloat162float(h0.y)));
                __nv_bfloat162 h1 = __float22bfloat162_rn(
                    make_float2(sacc[nt2][2], sacc[nt2][3]));
                __nv_bfloat162 l1p = __float22bfloat162_rn(
                    make_float2(sacc[nt2][2] - __bfloat162float(h1.x),
                                sacc[nt2][3] - __bfloat162float(h1.y)));
                pah[half * 2 + 0] = *(uint32_t*)&h0;
                pah[half * 2 + 1] = *(uint32_t*)&h1;
                pal[half * 2 + 0] = *(uint32_t*)&l0p;
                pal[half * 2 + 1] = *(uint32_t*)&l1p;
            }
#pragma unroll
            for (int nt = 0; nt < 16; nt++) {
                int bo = (8 * nt + g) * VROWW + 8 * kt + tg;
                uint32_t bh0 = sw[SV + bo], bh1 = sw[SV + bo + 4];
                uint32_t bl0 = sw[SVl + bo], bl1 = sw[SVl + bo + 4];
                mma16816(o[nt][0], o[nt][1], o[nt][2], o[nt][3],
                         pah[0], pah[1], pah[2], pah[3], bh0, bh1);
                mma16816(o[nt][0], o[nt][1], o[nt][2], o[nt][3],
                         pal[0], pal[1], pal[2], pal[3], bh0, bh1);
                mma16816(o[nt][0], o[nt][1], o[nt][2], o[nt][3],
                         pah[0], pah[1], pah[2], pah[3], bl0, bl1);
            }
        }

        __syncthreads();
        if (kb + 2 < NKB) issue(kb + 2, s);
        CP_COMMIT();
    }

    float inv0 = 1.0f / l0, inv1 = 1.0f / l1;
    int row = q0 + rw + g;
#pragma unroll
    for (int nt = 0; nt < 16; nt++) {
        int col = h * HD + 8 * nt + 2 * tg;
        *(float2*)&g_att[(size_t)row * DIM + col] =
            make_float2(o[nt][0] * inv0, o[nt][1] * inv0);
        *(float2*)&g_att[(size_t)(row + 8) * DIM + col] =
            make_float2(o[nt][2] * inv1, o[nt][3] * inv1);
    }
}

// ---------------- launch ------------------------------------------------------
extern "C" void kernel_launch(void* const* d_in, const int* in_sizes, int n_in,
                              void* d_out, int out_size)
{
    const float* x    = (const float*)d_in[0];
    const float* q_w  = (const float*)d_in[1];
    const float* q_b  = (const float*)d_in[2];
    const float* k_w  = (const float*)d_in[3];
    const float* k_b  = (const float*)d_in[4];
    const float* v_w  = (const float*)d_in[5];
    const float* v_b  = (const float*)d_in[6];
    const float* o_w  = (const float*)d_in[7];
    const float* o_b  = (const float*)d_in[8];
    const float* nqw  = (const float*)d_in[9];
    const float* nkw  = (const float*)d_in[10];
    const float* freqs = (const float*)d_in[11];
    float* out = (float*)d_out;

    cudaFuncSetAttribute(attn_tc, cudaFuncAttributeMaxDynamicSharedMemorySize,
                         ATT_SMEM);
    cudaFuncSetAttribute(hgemm, cudaFuncAttributeMaxDynamicSharedMemorySize,
                         HG_SMEM);

    split_act<<<SEQ * DIM / 1024, 256>>>(x, 0);
    transpose_split<<<dim3(DIM / 32, DIM / 32, 4), dim3(32, 8)>>>(q_w, k_w, v_w, o_w);

    // fused QKV projections (gridDim.z = 3)
    hgemm<<<dim3(DIM / 128, SEQ / 128, 3), 256, HG_SMEM>>>(
        0, 0, q_b, k_b, v_b, o_b, nullptr);

    normrope_kernel<<<dim3(SEQ, 2), 256>>>(nqw, nkw, freqs);
    transpose_v<<<dim3(SEQ / 32, HD / 32, NH), dim3(32, 8)>>>();

    attn_tc<<<dim3(SEQ / 128, NH), 256, ATT_SMEM>>>();

    split_act<<<SEQ * DIM / 1024, 256>>>(nullptr, 1);
    hgemm<<<dim3(DIM / 128, SEQ / 128, 1), 256, HG_SMEM>>>(
        1, 3, q_b, k_b, v_b, o_b, out);
}

// round 9
// speedup vs baseline: 2.1149x; 1.0300x over previous
#include <cuda_runtime.h>
#include <cuda_bf16.h>
#include <math.h>
#include <stdint.h>

#define SEQ   3840
#define DIM   1536
#define NH    12
#define HD    128
#define HG    20
#define WG    24
#define D_F   22
#define D_FH  43

typedef unsigned long long u64;

// ---------------- scratch (device globals; no runtime allocation) -------------
__device__ float g_q[SEQ * DIM];
__device__ float g_k[SEQ * DIM];
__device__ float g_v[SEQ * DIM];

__device__ __nv_bfloat16 g_xh[SEQ * DIM], g_xl[SEQ * DIM];       // x split
__device__ __nv_bfloat16 g_ah[SEQ * DIM], g_al[SEQ * DIM];       // att split
__device__ __nv_bfloat16 g_wh[4][DIM * DIM], g_wl[4][DIM * DIM]; // W^T splits

// attention operands, head-major bf16 hi/lo
__device__ __nv_bfloat16 g_qbh[NH * SEQ * HD], g_qbl[NH * SEQ * HD]; // [h][s][d]
__device__ __nv_bfloat16 g_kbh[NH * SEQ * HD], g_kbl[NH * SEQ * HD]; // [h][s][d]
__device__ __nv_bfloat16 g_vth[NH * HD * SEQ], g_vtl[NH * HD * SEQ]; // [h][d][s]

// ---------------- helpers -----------------------------------------------------
__device__ __forceinline__ uint32_t smem_u32(const void* p) {
    uint32_t a;
    asm("{ .reg .u64 t; cvta.to.shared.u64 t, %1; cvt.u32.u64 %0, t; }"
        : "=r"(a) : "l"(p));
    return a;
}
__device__ __forceinline__ void cpasync16(uint32_t saddr, const void* g) {
    asm volatile("cp.async.cg.shared.global [%0], [%1], 16;"
                 :: "r"(saddr), "l"(g) : "memory");
}
#define CP_COMMIT() asm volatile("cp.async.commit_group;" ::: "memory")
#define CP_WAIT0()  asm volatile("cp.async.wait_group 0;" ::: "memory")
#define CP_WAIT1()  asm volatile("cp.async.wait_group 1;" ::: "memory")

__device__ __forceinline__ void mma16816(float& d0, float& d1, float& d2, float& d3,
                                         uint32_t a0, uint32_t a1, uint32_t a2,
                                         uint32_t a3, uint32_t b0, uint32_t b1) {
    asm volatile(
        "mma.sync.aligned.m16n8k16.row.col.f32.bf16.bf16.f32 "
        "{%0,%1,%2,%3}, {%4,%5,%6,%7}, {%8,%9}, {%0,%1,%2,%3};"
        : "+f"(d0), "+f"(d1), "+f"(d2), "+f"(d3)
        : "r"(a0), "r"(a1), "r"(a2), "r"(a3), "r"(b0), "r"(b1));
}
#define LDSM4(r0, r1, r2, r3, addr) \
    asm volatile("ldmatrix.sync.aligned.m8n8.x4.shared.b16 {%0,%1,%2,%3}, [%4];" \
        : "=r"(r0), "=r"(r1), "=r"(r2), "=r"(r3) : "r"(addr))

// ---------------- prep: split activations into bf16 hi/lo ---------------------
__global__ void split_act(const float* __restrict__ src)
{
    int i = (blockIdx.x * 256 + threadIdx.x) * 4;
    float4 v = *(const float4*)&src[i];
    __nv_bfloat16 h0 = __float2bfloat16(v.x), h1 = __float2bfloat16(v.y);
    __nv_bfloat16 h2 = __float2bfloat16(v.z), h3 = __float2bfloat16(v.w);
    __nv_bfloat16 l0 = __float2bfloat16(v.x - __bfloat162float(h0));
    __nv_bfloat16 l1 = __float2bfloat16(v.y - __bfloat162float(h1));
    __nv_bfloat16 l2 = __float2bfloat16(v.z - __bfloat162float(h2));
    __nv_bfloat16 l3 = __float2bfloat16(v.w - __bfloat162float(h3));
    ushort4 hh, ll;
    hh.x = *(unsigned short*)&h0; hh.y = *(unsigned short*)&h1;
    hh.z = *(unsigned short*)&h2; hh.w = *(unsigned short*)&h3;
    ll.x = *(unsigned short*)&l0; ll.y = *(unsigned short*)&l1;
    ll.z = *(unsigned short*)&l2; ll.w = *(unsigned short*)&l3;
    *(ushort4*)&g_xh[i] = hh;
    *(ushort4*)&g_xl[i] = ll;
}

// ---------------- prep: transpose + split weights ------------------------------
__global__ void transpose_split(const float* __restrict__ w0,
                                const float* __restrict__ w1,
                                const float* __restrict__ w2,
                                const float* __restrict__ w3)
{
    const float* W = (blockIdx.z == 0) ? w0 : (blockIdx.z == 1) ? w1
                   : (blockIdx.z == 2) ? w2 : w3;
    __nv_bfloat16* Oh = g_wh[blockIdx.z];
    __nv_bfloat16* Ol = g_wl[blockIdx.z];

    __shared__ float t[32][33];
    int k0 = blockIdx.y * 32, n0 = blockIdx.x * 32;
    int tx = threadIdx.x, ty = threadIdx.y;
#pragma unroll
    for (int j = 0; j < 4; j++)
        t[ty + j * 8][tx] = W[(size_t)(k0 + ty + j * 8) * DIM + n0 + tx];
    __syncthreads();
#pragma unroll
    for (int j = 0; j < 4; j++) {
        float v = t[tx][ty + j * 8];
        __nv_bfloat16 h = __float2bfloat16(v);
        __nv_bfloat16 l = __float2bfloat16(v - __bfloat162float(h));
        size_t o = (size_t)(n0 + ty + j * 8) * DIM + k0 + tx;
        Oh[o] = h;
        Ol[o] = l;
    }
}

// ---------------- prep: transpose V to [h][d][s] bf16 hi/lo --------------------
__global__ void transpose_v()
{
    __shared__ float t[32][33];
    int s0 = blockIdx.x * 32, d0 = blockIdx.y * 32, h = blockIdx.z;
    int tx = threadIdx.x, ty = threadIdx.y;
#pragma unroll
    for (int j = 0; j < 4; j++)
        t[ty + j * 8][tx] = g_v[(size_t)(s0 + ty + j * 8) * DIM + h * HD + d0 + tx];
    __syncthreads();
#pragma unroll
    for (int j = 0; j < 4; j++) {
        float v = t[tx][ty + j * 8];
        __nv_bfloat16 hb = __float2bfloat16(v);
        __nv_bfloat16 lb = __float2bfloat16(v - __bfloat162float(hb));
        size_t o = ((size_t)h * HD + d0 + ty + j * 8) * SEQ + s0 + tx;
        g_vth[o] = hb;
        g_vtl[o] = lb;
    }
}

// ---------------- mma.sync bf16x3 GEMM, double-buffered + ldmatrix -------------
#define TS 40
#define TILEB (128 * TS * 2)            // 10240 B per tile
#define GSTAGE (4 * TILEB)              // 40960 B per stage
#define HG_SMEM (2 * GSTAGE)            // 81920 B
#define NCH (DIM / 32)                  // 48 chunks

__global__ __launch_bounds__(256, 2)
void hgemm(int asel, int wbase,
           const float* __restrict__ b0, const float* __restrict__ b1,
           const float* __restrict__ b2, const float* __restrict__ b3,
           float* __restrict__ Cout)
{
    extern __shared__ char hsm[];
    int wsel = wbase + blockIdx.z;
    const __nv_bfloat16* Agh = asel ? g_ah : g_xh;
    const __nv_bfloat16* Agl = asel ? g_al : g_xl;
    const __nv_bfloat16* Bgh = g_wh[wsel];
    const __nv_bfloat16* Bgl = g_wl[wsel];
    const float* bias = (wsel == 0) ? b0 : (wsel == 1) ? b1 : (wsel == 2) ? b2 : b3;
    float* C = (wsel == 0) ? g_q : (wsel == 1) ? g_k : (wsel == 2) ? g_v : Cout;

    uint32_t sbase = smem_u32(hsm);

    int tid = threadIdx.x, wid = tid >> 5, lid = tid & 31;
    int wm = wid >> 2, wn = wid & 3;
    int g = lid >> 2, tg = lid & 3;
    int m0 = blockIdx.y * 128, n0 = blockIdx.x * 128;

    // ldmatrix per-lane address components (bytes within a tile)
    int lr = lid & 7;
    uint32_t aoffb = ((wm * 64 + ((lid >> 3) & 1) * 8 + lr) * TS + (lid >> 4) * 8) * 2;
    uint32_t boffb = ((wn * 32 + (lid >> 4) * 8 + lr) * TS + ((lid >> 3) & 1) * 8) * 2;

    // copy map
    int r0 = tid >> 2, sc0 = tid & 3;
    int r1 = (tid + 256) >> 2;
    uint32_t so0 = r0 * (TS * 2) + sc0 * 16;
    uint32_t so1 = r1 * (TS * 2) + sc0 * 16;

    float acc[4][4][4];
#pragma unroll
    for (int t = 0; t < 4; t++)
#pragma unroll
        for (int u = 0; u < 4; u++)
#pragma unroll
            for (int c = 0; c < 4; c++) acc[t][u][c] = 0.f;

    auto issue = [&](int ch, int s) {
        uint32_t sb = sbase + s * GSTAGE;
        size_t ga0 = (size_t)(m0 + r0) * DIM + ch * 32 + sc0 * 8;
        size_t ga1 = (size_t)(m0 + r1) * DIM + ch * 32 + sc0 * 8;
        size_t gb0 = (size_t)(n0 + r0) * DIM + ch * 32 + sc0 * 8;
        size_t gb1 = (size_t)(n0 + r1) * DIM + ch * 32 + sc0 * 8;
        cpasync16(sb + so0, &Agh[ga0]);
        cpasync16(sb + so1, &Agh[ga1]);
        cpasync16(sb + TILEB + so0, &Agl[ga0]);
        cpasync16(sb + TILEB + so1, &Agl[ga1]);
        cpasync16(sb + 2 * TILEB + so0, &Bgh[gb0]);
        cpasync16(sb + 2 * TILEB + so1, &Bgh[gb1]);
        cpasync16(sb + 3 * TILEB + so0, &Bgl[gb0]);
        cpasync16(sb + 3 * TILEB + so1, &Bgl[gb1]);
    };

    issue(0, 0); CP_COMMIT();
    issue(1, 1); CP_COMMIT();

    for (int ch = 0; ch < NCH; ch++) {
        int s = ch & 1;
        CP_WAIT1();
        __syncthreads();

        uint32_t sb = sbase + s * GSTAGE;

#pragma unroll
        for (int ks = 0; ks < 2; ks++) {
            uint32_t kcb = ks * 32;   // 16 bf16 = 32 bytes

            uint32_t ah[4][4], bh[2][4];
#pragma unroll
            for (int t = 0; t < 4; t++)
                LDSM4(ah[t][0], ah[t][1], ah[t][2], ah[t][3],
                      sb + aoffb + t * (16 * TS * 2) + kcb);
            LDSM4(bh[0][0], bh[0][1], bh[0][2], bh[0][3],
                  sb + 2 * TILEB + boffb + kcb);
            LDSM4(bh[1][0], bh[1][1], bh[1][2], bh[1][3],
                  sb + 2 * TILEB + boffb + (16 * TS * 2) + kcb);

            // pass1: Ah * Bh
#pragma unroll
            for (int t = 0; t < 4; t++)
#pragma unroll
                for (int u = 0; u < 4; u++)
                    mma16816(acc[t][u][0], acc[t][u][1], acc[t][u][2], acc[t][u][3],
                             ah[t][0], ah[t][1], ah[t][2], ah[t][3],
                             bh[u >> 1][(u & 1) * 2], bh[u >> 1][(u & 1) * 2 + 1]);

            // pass2: Ah * Bl
            {
                uint32_t bl[2][4];
                LDSM4(bl[0][0], bl[0][1], bl[0][2], bl[0][3],
                      sb + 3 * TILEB + boffb + kcb);
                LDSM4(bl[1][0], bl[1][1], bl[1][2], bl[1][3],
                      sb + 3 * TILEB + boffb + (16 * TS * 2) + kcb);
#pragma unroll
                for (int t = 0; t < 4; t++)
#pragma unroll
                    for (int u = 0; u < 4; u++)
                        mma16816(acc[t][u][0], acc[t][u][1], acc[t][u][2], acc[t][u][3],
                                 ah[t][0], ah[t][1], ah[t][2], ah[t][3],
                                 bl[u >> 1][(u & 1) * 2], bl[u >> 1][(u & 1) * 2 + 1]);
            }

            // pass3: Al * Bh
            {
                uint32_t al[4][4];
#pragma unroll
                for (int t = 0; t < 4; t++)
                    LDSM4(al[t][0], al[t][1], al[t][2], al[t][3],
                          sb + TILEB + aoffb + t * (16 * TS * 2) + kcb);
#pragma unroll
                for (int t = 0; t < 4; t++)
#pragma unroll
                    for (int u = 0; u < 4; u++)
                        mma16816(acc[t][u][0], acc[t][u][1], acc[t][u][2], acc[t][u][3],
                                 al[t][0], al[t][1], al[t][2], al[t][3],
                                 bh[u >> 1][(u & 1) * 2], bh[u >> 1][(u & 1) * 2 + 1]);
            }
        }
        __syncthreads();
        if (ch + 2 < NCH) issue(ch + 2, s);
        CP_COMMIT();
    }

#pragma unroll
    for (int t = 0; t < 4; t++) {
        int row = m0 + wm * 64 + t * 16 + g;
#pragma unroll
        for (int u = 0; u < 4; u++) {
            int col = n0 + wn * 32 + u * 8 + tg * 2;
            float2 bv = *(const float2*)&bias[col];
            float2 lo = make_float2(acc[t][u][0] + bv.x, acc[t][u][1] + bv.y);
            float2 hi = make_float2(acc[t][u][2] + bv.x, acc[t][u][3] + bv.y);
            *(float2*)&C[(size_t)row * DIM + col] = lo;
            *(float2*)&C[(size_t)(row + 8) * DIM + col] = hi;
        }
    }
}

// ---------------- RMSNorm + RoPE -> bf16 hi/lo head-major ----------------------
__global__ void normrope_kernel(const float* __restrict__ nqw,
                                const float* __restrict__ nkw,
                                const float* __restrict__ freqs)
{
    int s = blockIdx.x;
    bool isq = (blockIdx.y == 0);
    const float* buf = (isq ? g_q : g_k) + (size_t)s * DIM;
    const float* w = isq ? nqw : nkw;
    __nv_bfloat16* outh = isq ? g_qbh : g_kbh;
    __nv_bfloat16* outl = isq ? g_qbl : g_kbl;
    float oscale = isq ? 0.08838834764831845f : 1.0f;

    __shared__ float row[DIM];
    __shared__ float red[8];

    int tid = threadIdx.x;
    float ss = 0.f;
    for (int i = tid; i < DIM; i += 256) {
        float v = buf[i];
        row[i] = v;
        ss += v * v;
    }
#pragma unroll
    for (int o = 16; o; o >>= 1) ss += __shfl_xor_sync(0xffffffff, ss, o);
    if ((tid & 31) == 0) red[tid >> 5] = ss;
    __syncthreads();
    if (tid < 8) {
        float t = red[tid];
#pragma unroll
        for (int o = 4; o; o >>= 1) t += __shfl_xor_sync(0xff, t, o);
        if (tid == 0) red[0] = t;
    }
    __syncthreads();
    float r = rsqrtf(red[0] / (float)DIM + 1e-6f);

    int fi = s / (HG * WG);
    int rem = s % (HG * WG);
    int hi = rem / WG;
    int wi = rem % WG;

    for (int p = tid; p < NH * 64; p += 256) {
        int h = p >> 6, c = p & 63;
        int pos = (c < D_F) ? fi : (c < D_FH) ? hi : wi;
        float ang = freqs[pos * 64 + c];
        float sn, cs;
        sincosf(ang, &sn, &cs);
        int j = h * HD + 2 * c;
        float y0 = row[j] * r * w[j];
        float y1 = row[j + 1] * r * w[j + 1];
        float v0 = (y0 * cs - y1 * sn) * oscale;
        float v1 = (y0 * sn + y1 * cs) * oscale;
        __nv_bfloat162 hh = __float22bfloat162_rn(make_float2(v0, v1));
        float r0 = v0 - __bfloat162float(hh.x);
        float r1 = v1 - __bfloat162float(hh.y);
        __nv_bfloat162 ll = __float22bfloat162_rn(make_float2(r0, r1));
        size_t off = ((size_t)h * SEQ + s) * HD + 2 * c;
        *(__nv_bfloat162*)&outh[off] = hh;
        *(__nv_bfloat162*)&outl[off] = ll;
    }
}

// ---------------- tensor-core flash attention (bf16x3) -------------------------
#define KROWB   272
#define KROWW   68
#define VROWB   144
#define VROWW   36
#define SZKB    (64 * KROWB)
#define SZVB    (128 * VROWB)
#define STAGEB  (2 * SZKB + 2 * SZVB)
#define ATT_SMEM (2 * STAGEB)
#define NKB     (SEQ / 64)

__global__ __launch_bounds__(256, 1)
void attn_tc()
{
    extern __shared__ char smem[];
    uint32_t sbase = smem_u32(smem);
    uint32_t* sw = (uint32_t*)smem;

    int tid = threadIdx.x, wid = tid >> 5, lid = tid & 31;
    int g = lid >> 2, tg = lid & 3;
    int h = blockIdx.y;
    int q0 = blockIdx.x * 128;

#pragma unroll
    for (int i = 0; i < 8; i++) {
        int idx = tid + i * 256;
        int r = idx >> 4, sc = idx & 15;
        size_t gsrc = (((size_t)h * SEQ + q0 + r) * HD) * 2 + sc * 16;
        cpasync16(sbase + r * KROWB + sc * 16, (const char*)g_qbh + gsrc);
        cpasync16(sbase + 34816 + r * KROWB + sc * 16, (const char*)g_qbl + gsrc);
    }
    CP_COMMIT();
    CP_WAIT0();
    __syncthreads();

    uint32_t qh[8][4], ql[8][4];
    int rw = wid * 16;
#pragma unroll
    for (int kt = 0; kt < 8; kt++) {
        int base = (rw + g) * KROWW + 8 * kt + tg;
        int base8 = (rw + g + 8) * KROWW + 8 * kt + tg;
        qh[kt][0] = sw[base];
        qh[kt][1] = sw[base8];
        qh[kt][2] = sw[base + 4];
        qh[kt][3] = sw[base8 + 4];
        ql[kt][0] = sw[8704 + base];
        ql[kt][1] = sw[8704 + base8];
        ql[kt][2] = sw[8704 + base + 4];
        ql[kt][3] = sw[8704 + base8 + 4];
    }
    __syncthreads();

    float o[16][4];
#pragma unroll
    for (int nt = 0; nt < 16; nt++)
#pragma unroll
        for (int c = 0; c < 4; c++) o[nt][c] = 0.f;
    float m0 = -1e30f, m1 = -1e30f, l0 = 0.f, l1 = 0.f;

    auto issue = [&](int kb, int s) {
        int k0 = kb * 64;
        uint32_t sb = sbase + s * STAGEB;
#pragma unroll
        for (int i = 0; i < 4; i++) {
            int idx = tid + i * 256;
            int r = idx >> 4, sc = idx & 15;
            size_t gk = (((size_t)h * SEQ + k0 + r) * HD) * 2 + sc * 16;
            cpasync16(sb + r * KROWB + sc * 16, (const char*)g_kbh + gk);
            cpasync16(sb + SZKB + r * KROWB + sc * 16, (const char*)g_kbl + gk);
        }
#pragma unroll
        for (int i = 0; i < 4; i++) {
            int idx = tid + i * 256;
            int d = idx >> 3, sc = idx & 7;
            size_t gv = (((size_t)h * HD + d) * SEQ + k0) * 2 + sc * 16;
            cpasync16(sb + 2 * SZKB + d * VROWB + sc * 16, (const char*)g_vth + gv);
            cpasync16(sb + 2 * SZKB + SZVB + d * VROWB + sc * 16,
                      (const char*)g_vtl + gv);
        }
    };

    issue(0, 0); CP_COMMIT();
    issue(1, 1); CP_COMMIT();

    for (int kb = 0; kb < NKB; kb++) {
        int s = kb & 1;
        CP_WAIT1();
        __syncthreads();

        uint32_t SK = s * (STAGEB / 4);
        uint32_t SKl = SK + SZKB / 4;
        uint32_t SV = SK + 2 * (SZKB / 4);
        uint32_t SVl = SV + SZVB / 4;

        float sacc[8][4];
#pragma unroll
        for (int nt = 0; nt < 8; nt++)
#pragma unroll
            for (int c = 0; c < 4; c++) sacc[nt][c] = 0.f;

#pragma unroll
        for (int kt = 0; kt < 8; kt++) {
#pragma unroll
            for (int nt = 0; nt < 8; nt++) {
                int bo = (8 * nt + g) * KROWW + 8 * kt + tg;
                uint32_t bh0 = sw[SK + bo], bh1 = sw[SK + bo + 4];
                uint32_t bl0 = sw[SKl + bo], bl1 = sw[SKl + bo + 4];
                mma16816(sacc[nt][0], sacc[nt][1], sacc[nt][2], sacc[nt][3],
                         qh[kt][0], qh[kt][1], qh[kt][2], qh[kt][3], bh0, bh1);
                mma16816(sacc[nt][0], sacc[nt][1], sacc[nt][2], sacc[nt][3],
                         ql[kt][0], ql[kt][1], ql[kt][2], ql[kt][3], bh0, bh1);
                mma16816(sacc[nt][0], sacc[nt][1], sacc[nt][2], sacc[nt][3],
                         qh[kt][0], qh[kt][1], qh[kt][2], qh[kt][3], bl0, bl1);
            }
        }

        float mx0 = -1e30f, mx1 = -1e30f;
#pragma unroll
        for (int nt = 0; nt < 8; nt++) {
            mx0 = fmaxf(mx0, fmaxf(sacc[nt][0], sacc[nt][1]));
            mx1 = fmaxf(mx1, fmaxf(sacc[nt][2], sacc[nt][3]));
        }
        mx0 = fmaxf(mx0, __shfl_xor_sync(0xffffffffu, mx0, 1));
        mx0 = fmaxf(mx0, __shfl_xor_sync(0xffffffffu, mx0, 2));
        mx1 = fmaxf(mx1, __shfl_xor_sync(0xffffffffu, mx1, 1));
        mx1 = fmaxf(mx1, __shfl_xor_sync(0xffffffffu, mx1, 2));
        float mn0 = fmaxf(m0, mx0), mn1 = fmaxf(m1, mx1);
        float corr0 = __expf(m0 - mn0), corr1 = __expf(m1 - mn1);
        m0 = mn0; m1 = mn1;
        float ls0 = 0.f, ls1 = 0.f;
#pragma unroll
        for (int nt = 0; nt < 8; nt++) {
            sacc[nt][0] = __expf(sacc[nt][0] - m0); ls0 += sacc[nt][0];
            sacc[nt][1] = __expf(sacc[nt][1] - m0); ls0 += sacc[nt][1];
            sacc[nt][2] = __expf(sacc[nt][2] - m1); ls1 += sacc[nt][2];
            sacc[nt][3] = __expf(sacc[nt][3] - m1); ls1 += sacc[nt][3];
        }
        ls0 += __shfl_xor_sync(0xffffffffu, ls0, 1);
        ls0 += __shfl_xor_sync(0xffffffffu, ls0, 2);
        ls1 += __shfl_xor_sync(0xffffffffu, ls1, 1);
        ls1 += __shfl_xor_sync(0xffffffffu, ls1, 2);
        l0 = l0 * corr0 + ls0;
        l1 = l1 * corr1 + ls1;

#pragma unroll
        for (int nt = 0; nt < 16; nt++) {
            o[nt][0] *= corr0; o[nt][1] *= corr0;
            o[nt][2] *= corr1; o[nt][3] *= corr1;
        }

#pragma unroll
        for (int kt = 0; kt < 4; kt++) {
            uint32_t pah[4], pal[4];
#pragma unroll
            for (int half = 0; half < 2; half++) {
                int nt2 = 2 * kt + half;
                __nv_bfloat162 h0 = __float22bfloat162_rn(
                    make_float2(sacc[nt2][0], sacc[nt2][1]));
                __nv_bfloat162 l0p = __float22bfloat162_rn(
                    make_float2(sacc[nt2][0] - __bfloat162float(h0.x),
                                sacc[nt2][1] - __bfloat162float(h0.y)));
                __nv_bfloat162 h1 = __float22bfloat162_rn(
                    make_float2(sacc[nt2][2], sacc[nt2][3]));
                __nv_bfloat162 l1p = __float22bfloat162_rn(
                    make_float2(sacc[nt2][2] - __bfloat162float(h1.x),
                                sacc[nt2][3] - __bfloat162float(h1.y)));
                pah[half * 2 + 0] = *(uint32_t*)&h0;
                pah[half * 2 + 1] = *(uint32_t*)&h1;
                pal[half * 2 + 0] = *(uint32_t*)&l0p;
                pal[half * 2 + 1] = *(uint32_t*)&l1p;
            }
#pragma unroll
            for (int nt = 0; nt < 16; nt++) {
                int bo = (8 * nt + g) * VROWW + 8 * kt + tg;
                uint32_t bh0 = sw[SV + bo], bh1 = sw[SV + bo + 4];
                uint32_t bl0 = sw[SVl + bo], bl1 = sw[SVl + bo + 4];
                mma16816(o[nt][0], o[nt][1], o[nt][2], o[nt][3],
                         pah[0], pah[1], pah[2], pah[3], bh0, bh1);
                mma16816(o[nt][0], o[nt][1], o[nt][2], o[nt][3],
                         pal[0], pal[1], pal[2], pal[3], bh0, bh1);
                mma16816(o[nt][0], o[nt][1], o[nt][2], o[nt][3],
                         pah[0], pah[1], pah[2], pah[3], bl0, bl1);
            }
        }

        __syncthreads();
        if (kb + 2 < NKB) issue(kb + 2, s);
        CP_COMMIT();
    }

    // ---- normalize + store directly as bf16 hi/lo (feeds O-projection) ----
    float inv0 = 1.0f / l0, inv1 = 1.0f / l1;
    int row = q0 + rw + g;
#pragma unroll
    for (int nt = 0; nt < 16; nt++) {
        int col = h * HD + 8 * nt + 2 * tg;
        float v0 = o[nt][0] * inv0, v1 = o[nt][1] * inv0;
        float v2 = o[nt][2] * inv1, v3 = o[nt][3] * inv1;
        __nv_bfloat162 h0 = __float22bfloat162_rn(make_float2(v0, v1));
        __nv_bfloat162 l0p = __float22bfloat162_rn(
            make_float2(v0 - __bfloat162float(h0.x), v1 - __bfloat162float(h0.y)));
        __nv_bfloat162 h1 = __float22bfloat162_rn(make_float2(v2, v3));
        __nv_bfloat162 l1p = __float22bfloat162_rn(
            make_float2(v2 - __bfloat162float(h1.x), v3 - __bfloat162float(h1.y)));
        *(__nv_bfloat162*)&g_ah[(size_t)row * DIM + col] = h0;
        *(__nv_bfloat162*)&g_al[(size_t)row * DIM + col] = l0p;
        *(__nv_bfloat162*)&g_ah[(size_t)(row + 8) * DIM + col] = h1;
        *(__nv_bfloat162*)&g_al[(size_t)(row + 8) * DIM + col] = l1p;
    }
}

// ---------------- launch ------------------------------------------------------
extern "C" void kernel_launch(void* const* d_in, const int* in_sizes, int n_in,
                              void* d_out, int out_size)
{
    const float* x    = (const float*)d_in[0];
    const float* q_w  = (const float*)d_in[1];
    const float* q_b  = (const float*)d_in[2];
    const float* k_w  = (const float*)d_in[3];
    const float* k_b  = (const float*)d_in[4];
    const float* v_w  = (const float*)d_in[5];
    const float* v_b  = (const float*)d_in[6];
    const float* o_w  = (const float*)d_in[7];
    const float* o_b  = (const float*)d_in[8];
    const float* nqw  = (const float*)d_in[9];
    const float* nkw  = (const float*)d_in[10];
    const float* freqs = (const float*)d_in[11];
    float* out = (float*)d_out;

    cudaFuncSetAttribute(attn_tc, cudaFuncAttributeMaxDynamicSharedMemorySize,
                         ATT_SMEM);
    cudaFuncSetAttribute(hgemm, cudaFuncAttributeMaxDynamicSharedMemorySize,
                         HG_SMEM);

    split_act<<<SEQ * DIM / 1024, 256>>>(x);
    transpose_split<<<dim3(DIM / 32, DIM / 32, 4), dim3(32, 8)>>>(q_w, k_w, v_w, o_w);

    // fused QKV projections (gridDim.z = 3)
    hgemm<<<dim3(DIM / 128, SEQ / 128, 3), 256, HG_SMEM>>>(
        0, 0, q_b, k_b, v_b, o_b, nullptr);

    normrope_kernel<<<dim3(SEQ, 2), 256>>>(nqw, nkw, freqs);
    transpose_v<<<dim3(SEQ / 32, HD / 32, NH), dim3(32, 8)>>>();

    attn_tc<<<dim3(SEQ / 128, NH), 256, ATT_SMEM>>>();

    hgemm<<<dim3(DIM / 128, SEQ / 128, 1), 256, HG_SMEM>>>(
        1, 3, q_b, k_b, v_b, o_b, out);
}